// round 2
// baseline (speedup 1.0000x reference)
#include <cuda_runtime.h>
#include <cuda_bf16.h>
#include <math.h>

// ---------------------------------------------------------------------------
// Problem dims (fixed by the reference)
// ---------------------------------------------------------------------------
#define BB   16
#define SS   256
#define NH   12
#define HD   64
#define HID  768
#define FFND 3072
#define NL   6
#define NT   9
#define MTOK (BB*SS)          // 4096 tokens

// ---------------------------------------------------------------------------
// Scratch (device globals -- allowed; no runtime allocation)
// ---------------------------------------------------------------------------
__device__ float g_x   [MTOK*HID];     // residual stream
__device__ float g_qkv [MTOK*3*HID];   // qkv projections
__device__ float g_att [BB*NH*SS*SS];  // attention scores / probs
__device__ float g_o   [MTOK*HID];     // attention output (pre-proj)
__device__ float g_ffn [MTOK*FFND];    // ffn intermediate
__device__ float g_tmp [MTOK*HID];     // gemm output temp
__device__ float g_lg  [MTOK*NT];      // logits

// ---------------------------------------------------------------------------
// Block-wide sum over 256 threads (all threads get the result)
// ---------------------------------------------------------------------------
__device__ __forceinline__ float blk_sum256(float v) {
    __shared__ float sm[8];
    #pragma unroll
    for (int o = 16; o; o >>= 1) v += __shfl_xor_sync(0xffffffffu, v, o);
    if ((threadIdx.x & 31) == 0) sm[threadIdx.x >> 5] = v;
    __syncthreads();
    float tot = 0.f;
    #pragma unroll
    for (int i = 0; i < 8; i++) tot += sm[i];
    __syncthreads();
    return tot;
}

// ---------------------------------------------------------------------------
// Embedding gather + LayerNorm.  grid = 4096 blocks x 256 thr
// ---------------------------------------------------------------------------
__global__ __launch_bounds__(256) void embed_ln_kernel(
    const int* __restrict__ ids, const float* __restrict__ wemb,
    const float* __restrict__ pemb, const float* __restrict__ lns,
    const float* __restrict__ lnb, float* __restrict__ x)
{
    int tok = blockIdx.x;
    int sp  = tok % SS;
    long id = ids[tok];
    float v[3]; float s = 0.f;
    #pragma unroll
    for (int j = 0; j < 3; j++) {
        int idx = threadIdx.x + j*256;
        v[j] = wemb[id*HID + idx] + pemb[(long)sp*HID + idx];
        s += v[j];
    }
    float mean = blk_sum256(s) * (1.f/HID);
    float sv = 0.f;
    #pragma unroll
    for (int j = 0; j < 3; j++) { float d = v[j]-mean; sv += d*d; }
    float var = blk_sum256(sv) * (1.f/HID);
    float inv = rsqrtf(var + 1e-12f);
    #pragma unroll
    for (int j = 0; j < 3; j++) {
        int idx = threadIdx.x + j*256;
        x[(long)tok*HID + idx] = (v[j]-mean)*inv*lns[idx] + lnb[idx];
    }
}

// ---------------------------------------------------------------------------
// SGEMM  C[M,N] = act(A[M,K] @ W[K,N] + bias[N])
// BM=128, BN=64, BK=16, 256 thr, 8x4 per thread.  M % 128 == 0, N % 64 == 0,
// K % 16 == 0.  FUSE_GELU applies tanh-gelu in the epilogue.
// ---------------------------------------------------------------------------
template<bool FUSE_GELU>
__global__ __launch_bounds__(256) void sgemm_bias_kernel(
    const float* __restrict__ A, const float* __restrict__ W,
    const float* __restrict__ bias, float* __restrict__ C,
    int M, int N, int K)
{
    __shared__ float As[16][136];   // [kk][row], padded
    __shared__ float Bs[16][64];    // [kk][col]
    int tx = threadIdx.x & 15;      // 16 col groups of 4
    int ty = threadIdx.x >> 4;      // 16 row groups of 8
    int row0 = blockIdx.y * 128, col0 = blockIdx.x * 64;
    float acc[8][4] = {};
    for (int k0 = 0; k0 < K; k0 += 16) {
        #pragma unroll
        for (int i = threadIdx.x; i < 128*16; i += 256) {
            int r = i >> 4, kk = i & 15;
            As[kk][r] = A[(long)(row0+r)*K + k0 + kk];
        }
        #pragma unroll
        for (int i = threadIdx.x; i < 16*64; i += 256) {
            int kk = i >> 6, c = i & 63;
            Bs[kk][c] = W[(long)(k0+kk)*N + col0 + c];
        }
        __syncthreads();
        #pragma unroll
        for (int kk = 0; kk < 16; kk++) {
            float a[8], b[4];
            *(float4*)&a[0] = *(const float4*)&As[kk][ty*8];
            *(float4*)&a[4] = *(const float4*)&As[kk][ty*8+4];
            *(float4*)&b[0] = *(const float4*)&Bs[kk][tx*4];
            #pragma unroll
            for (int i = 0; i < 8; i++)
                #pragma unroll
                for (int j = 0; j < 4; j++) acc[i][j] += a[i]*b[j];
        }
        __syncthreads();
    }
    #pragma unroll
    for (int i = 0; i < 8; i++) {
        long r = row0 + ty*8 + i;
        #pragma unroll
        for (int j = 0; j < 4; j++) {
            int c = col0 + tx*4 + j;
            float v = acc[i][j] + bias[c];
            if (FUSE_GELU) {
                float t = tanhf(0.7978845608028654f * (v + 0.044715f*v*v*v));
                v = 0.5f * v * (1.f + t);
            }
            C[r*N + c] = v;
        }
    }
}

// ---------------------------------------------------------------------------
// Attention scores: att[bh,q,k] = (q . k)/8 + (1-mask[b,k])*-1e9
// grid (ktile=4, qtile=4, bh=192), 256 thr, 64x64 tile, Kdim=64
// ---------------------------------------------------------------------------
__global__ __launch_bounds__(256) void attn_scores_kernel(
    const float* __restrict__ qkv, const int* __restrict__ amask,
    float* __restrict__ att)
{
    int bh = blockIdx.z, b = bh / NH, h = bh % NH;
    int q0 = blockIdx.y * 64, k0 = blockIdx.x * 64;
    __shared__ float Qs[16][68];
    __shared__ float Ks[16][68];
    int tx = threadIdx.x & 15, ty = threadIdx.x >> 4;
    const float* qb = qkv + (long)(b*SS)*(3*HID) + h*HD;
    const float* kb = qkv + (long)(b*SS)*(3*HID) + HID + h*HD;
    float acc[4][4] = {};
    for (int d0 = 0; d0 < HD; d0 += 16) {
        #pragma unroll
        for (int i = threadIdx.x; i < 64*16; i += 256) {
            int r = i >> 4, dd = i & 15;
            Qs[dd][r] = qb[(long)(q0+r)*(3*HID) + d0 + dd];
            Ks[dd][r] = kb[(long)(k0+r)*(3*HID) + d0 + dd];
        }
        __syncthreads();
        #pragma unroll
        for (int dd = 0; dd < 16; dd++) {
            float a[4], bv[4];
            *(float4*)a  = *(const float4*)&Qs[dd][ty*4];
            *(float4*)bv = *(const float4*)&Ks[dd][tx*4];
            #pragma unroll
            for (int i = 0; i < 4; i++)
                #pragma unroll
                for (int j = 0; j < 4; j++) acc[i][j] += a[i]*bv[j];
        }
        __syncthreads();
    }
    float biasv[4];
    #pragma unroll
    for (int j = 0; j < 4; j++)
        biasv[j] = (1.f - (float)amask[b*SS + k0 + tx*4 + j]) * -1e9f;
    #pragma unroll
    for (int i = 0; i < 4; i++) {
        long r = (long)bh*SS + q0 + ty*4 + i;
        #pragma unroll
        for (int j = 0; j < 4; j++)
            att[r*SS + k0 + tx*4 + j] = acc[i][j]*0.125f + biasv[j];
    }
}

// ---------------------------------------------------------------------------
// Row softmax over 256 columns.  grid = B*H*S blocks of 256 thr
// ---------------------------------------------------------------------------
__global__ __launch_bounds__(256) void softmax_kernel(float* __restrict__ att)
{
    float* p = att + (long)blockIdx.x * SS;
    float v = p[threadIdx.x];
    __shared__ float sm[8];
    float m = v;
    #pragma unroll
    for (int o = 16; o; o >>= 1) m = fmaxf(m, __shfl_xor_sync(0xffffffffu, m, o));
    if ((threadIdx.x & 31) == 0) sm[threadIdx.x >> 5] = m;
    __syncthreads();
    float mx = -1e30f;
    #pragma unroll
    for (int i = 0; i < 8; i++) mx = fmaxf(mx, sm[i]);
    __syncthreads();
    float e = expf(v - mx);
    float s = e;
    #pragma unroll
    for (int o = 16; o; o >>= 1) s += __shfl_xor_sync(0xffffffffu, s, o);
    if ((threadIdx.x & 31) == 0) sm[threadIdx.x >> 5] = s;
    __syncthreads();
    float tot = 0.f;
    #pragma unroll
    for (int i = 0; i < 8; i++) tot += sm[i];
    p[threadIdx.x] = e / tot;
}

// ---------------------------------------------------------------------------
// AV: o[b, q, h*64+d] = sum_k att[bh,q,k] * v[b,k,h,d]
// grid (qtile=4, bh=192), 256 thr, tile 64(q) x 64(d), K=256
// ---------------------------------------------------------------------------
__global__ __launch_bounds__(256) void attn_av_kernel(
    const float* __restrict__ att, const float* __restrict__ qkv,
    float* __restrict__ o)
{
    int bh = blockIdx.y, b = bh / NH, h = bh % NH;
    int q0 = blockIdx.x * 64;
    __shared__ float As[16][68];
    __shared__ float Vs[16][64];
    int tx = threadIdx.x & 15, ty = threadIdx.x >> 4;
    const float* ar = att + ((long)bh*SS + q0)*SS;
    const float* vb = qkv + (long)(b*SS)*(3*HID) + 2*HID + h*HD;
    float acc[4][4] = {};
    for (int k0 = 0; k0 < SS; k0 += 16) {
        #pragma unroll
        for (int i = threadIdx.x; i < 64*16; i += 256) {
            int r = i >> 4, kk = i & 15;
            As[kk][r] = ar[(long)r*SS + k0 + kk];
        }
        #pragma unroll
        for (int i = threadIdx.x; i < 16*64; i += 256) {
            int kk = i >> 6, d = i & 63;
            Vs[kk][d] = vb[(long)(k0+kk)*(3*HID) + d];
        }
        __syncthreads();
        #pragma unroll
        for (int kk = 0; kk < 16; kk++) {
            float a[4], bv[4];
            *(float4*)a  = *(const float4*)&As[kk][ty*4];
            *(float4*)bv = *(const float4*)&Vs[kk][tx*4];
            #pragma unroll
            for (int i = 0; i < 4; i++)
                #pragma unroll
                for (int j = 0; j < 4; j++) acc[i][j] += a[i]*bv[j];
        }
        __syncthreads();
    }
    #pragma unroll
    for (int i = 0; i < 4; i++) {
        long r = (long)(b*SS + q0 + ty*4 + i)*HID + h*HD;
        #pragma unroll
        for (int j = 0; j < 4; j++) o[r + tx*4 + j] = acc[i][j];
    }
}

// ---------------------------------------------------------------------------
// x = LN(x + y)  (y already has bias from GEMM).  grid = 4096 x 256
// ---------------------------------------------------------------------------
__global__ __launch_bounds__(256) void add_ln_kernel(
    float* __restrict__ x, const float* __restrict__ y,
    const float* __restrict__ lns, const float* __restrict__ lnb)
{
    long base = (long)blockIdx.x * HID;
    float v[3]; float s = 0.f;
    #pragma unroll
    for (int j = 0; j < 3; j++) {
        int idx = threadIdx.x + j*256;
        v[j] = x[base+idx] + y[base+idx];
        s += v[j];
    }
    float mean = blk_sum256(s) * (1.f/HID);
    float sv = 0.f;
    #pragma unroll
    for (int j = 0; j < 3; j++) { float d = v[j]-mean; sv += d*d; }
    float var = blk_sum256(sv) * (1.f/HID);
    float inv = rsqrtf(var + 1e-12f);
    #pragma unroll
    for (int j = 0; j < 3; j++) {
        int idx = threadIdx.x + j*256;
        x[base+idx] = (v[j]-mean)*inv*lns[idx] + lnb[idx];
    }
}

// ---------------------------------------------------------------------------
// Classifier head: logits[tok, t] = x . Wcls[:,t] + bcls[t]. 288 thr (9 warps)
// Also mirrors logits into harness out buffer.
// ---------------------------------------------------------------------------
__global__ __launch_bounds__(288) void cls_kernel(
    const float* __restrict__ x, const float* __restrict__ Wc,
    const float* __restrict__ bc, float* __restrict__ logits,
    float* __restrict__ out_l)
{
    __shared__ float xs[HID];
    int tok = blockIdx.x;
    for (int i = threadIdx.x; i < HID; i += blockDim.x) xs[i] = x[(long)tok*HID + i];
    __syncthreads();
    int w = threadIdx.x >> 5, lane = threadIdx.x & 31;
    if (w < NT) {
        float acc = 0.f;
        for (int i = lane; i < HID; i += 32) acc += xs[i] * Wc[i*NT + w];
        #pragma unroll
        for (int o = 16; o; o >>= 1) acc += __shfl_down_sync(0xffffffffu, acc, o);
        if (lane == 0) {
            float val = acc + bc[w];
            logits[tok*NT + w] = val;
            if (out_l) out_l[tok*NT + w] = val;
        }
    }
}

// ---------------------------------------------------------------------------
// CRF NLL, exactly mirroring the reference. Single block, 256 threads.
// Threads [0,144): (b=t/9, j=t%9) run the forward scan.
// ---------------------------------------------------------------------------
__global__ __launch_bounds__(256) void crf_kernel(
    const float* __restrict__ logits, const int* __restrict__ labels,
    const float* __restrict__ cst, const float* __restrict__ cen,
    const float* __restrict__ ctr, float* __restrict__ out_loss)
{
    __shared__ float sc[BB][NT];
    __shared__ float tr[NT*NT];
    __shared__ float st[NT], en[NT];
    __shared__ float nb[BB], dn[BB];
    int t = threadIdx.x;
    if (t < NT*NT) tr[t] = ctr[t];
    if (t < NT) { st[t] = cst[t]; en[t] = cen[t]; }
    __syncthreads();

    int b = t / NT, j = t % NT;
    if (t < BB*NT) sc[b][j] = st[j] + logits[(long)(b*SS)*NT + j];

    // numerator (threads 0..15, no barriers inside)
    if (t < BB) {
        int bb = t;
        int lab0 = labels[bb*SS];
        int tag0 = (lab0 == -100) ? 0 : lab0;
        float num = st[tag0] + logits[(long)(bb*SS)*NT + tag0];
        int prev = tag0;
        int cnt = 1;   // mask[:,0] forced true
        for (int s = 1; s < SS; s++) {
            int lab = labels[bb*SS + s];
            bool m = (lab != -100);
            int tg = m ? lab : 0;
            if (m) {
                num += tr[prev*NT + tg] + logits[(long)(bb*SS + s)*NT + tg];
                cnt++;
            }
            prev = tg;
        }
        int se = cnt - 1;
        int lab_e = labels[bb*SS + se];
        int tag_e = (lab_e == -100) ? 0 : lab_e;
        if (se == 0) tag_e = tag0;
        num += en[tag_e];
        nb[bb] = num;
    }
    __syncthreads();

    // forward scan
    for (int s = 1; s < SS; s++) {
        float nv = 0.f;
        if (t < BB*NT) {
            int lab = labels[b*SS + s];
            bool m = (lab != -100);
            float e  = logits[(long)(b*SS + s)*NT + j];
            float mx = -1e30f;
            #pragma unroll
            for (int i = 0; i < NT; i++) mx = fmaxf(mx, sc[b][i] + tr[i*NT + j]);
            float sum = 0.f;
            #pragma unroll
            for (int i = 0; i < NT; i++) sum += expf(sc[b][i] + tr[i*NT + j] - mx);
            float ns = mx + logf(sum) + e;
            nv = m ? ns : sc[b][j];
        }
        __syncthreads();
        if (t < BB*NT) sc[b][j] = nv;
        __syncthreads();
    }

    // denominator
    if (t < BB) {
        float mx = -1e30f;
        #pragma unroll
        for (int i = 0; i < NT; i++) mx = fmaxf(mx, sc[t][i] + en[i]);
        float sum = 0.f;
        #pragma unroll
        for (int i = 0; i < NT; i++) sum += expf(sc[t][i] + en[i] - mx);
        dn[t] = mx + logf(sum);
    }
    __syncthreads();
    if (t == 0 && out_loss) {
        float acc = 0.f;
        for (int i = 0; i < BB; i++) acc += nb[i] - dn[i];
        *out_loss = -acc / BB;
    }
}

// ---------------------------------------------------------------------------
// Launch
// ---------------------------------------------------------------------------
extern "C" void kernel_launch(void* const* d_in, const int* in_sizes, int n_in,
                              void* d_out, int out_size)
{
    const int*   ids   = (const int*)  d_in[0];
    const int*   amask = (const int*)  d_in[1];
    const int*   labels= (const int*)  d_in[2];
    const float* wemb  = (const float*)d_in[3];
    const float* pemb  = (const float*)d_in[4];
    const float* elns  = (const float*)d_in[5];
    const float* elnb  = (const float*)d_in[6];
    const float* Wqkv  = (const float*)d_in[7];
    const float* bqkv  = (const float*)d_in[8];
    const float* Wo    = (const float*)d_in[9];
    const float* bo    = (const float*)d_in[10];
    const float* ln1s  = (const float*)d_in[11];
    const float* ln1b  = (const float*)d_in[12];
    const float* Wff1  = (const float*)d_in[13];
    const float* bff1  = (const float*)d_in[14];
    const float* Wff2  = (const float*)d_in[15];
    const float* bff2  = (const float*)d_in[16];
    const float* ln2s  = (const float*)d_in[17];
    const float* ln2b  = (const float*)d_in[18];
    const float* Wcls  = (const float*)d_in[19];
    const float* bcls  = (const float*)d_in[20];
    const float* cst   = (const float*)d_in[21];
    const float* cen   = (const float*)d_in[22];
    const float* ctr   = (const float*)d_in[23];
    float* out = (float*)d_out;

    float *x, *qkv, *att, *o, *ffn, *tmp, *lg;
    cudaGetSymbolAddress((void**)&x,   g_x);
    cudaGetSymbolAddress((void**)&qkv, g_qkv);
    cudaGetSymbolAddress((void**)&att, g_att);
    cudaGetSymbolAddress((void**)&o,   g_o);
    cudaGetSymbolAddress((void**)&ffn, g_ffn);
    cudaGetSymbolAddress((void**)&tmp, g_tmp);
    cudaGetSymbolAddress((void**)&lg,  g_lg);

    // Output layout: tuple(loss, logits) flattened -> [1 + 36864] floats.
    int logits_off = out_size - MTOK*NT;       // expected 1
    float* out_logits = (logits_off >= 0) ? out + logits_off : nullptr;
    float* out_loss   = (logits_off >= 1) ? out : nullptr;

    embed_ln_kernel<<<MTOK, 256>>>(ids, wemb, pemb, elns, elnb, x);

    for (int l = 0; l < NL; l++) {
        const float* wqkv = Wqkv + (long)l*HID*3*HID;
        const float* bq   = bqkv + (long)l*3*HID;
        const float* wo   = Wo   + (long)l*HID*HID;
        const float* bo_  = bo   + (long)l*HID;
        const float* s1   = ln1s + (long)l*HID;
        const float* b1   = ln1b + (long)l*HID;
        const float* w1   = Wff1 + (long)l*HID*FFND;
        const float* bf1  = bff1 + (long)l*FFND;
        const float* w2   = Wff2 + (long)l*FFND*HID;
        const float* bf2  = bff2 + (long)l*HID;
        const float* s2   = ln2s + (long)l*HID;
        const float* b2   = ln2b + (long)l*HID;

        sgemm_bias_kernel<false><<<dim3(3*HID/64, MTOK/128), 256>>>(x, wqkv, bq, qkv, MTOK, 3*HID, HID);
        attn_scores_kernel<<<dim3(SS/64, SS/64, BB*NH), 256>>>(qkv, amask, att);
        softmax_kernel<<<BB*NH*SS, 256>>>(att);
        attn_av_kernel<<<dim3(SS/64, BB*NH), 256>>>(att, qkv, o);
        sgemm_bias_kernel<false><<<dim3(HID/64, MTOK/128), 256>>>(o, wo, bo_, tmp, MTOK, HID, HID);
        add_ln_kernel<<<MTOK, 256>>>(x, tmp, s1, b1);
        sgemm_bias_kernel<true><<<dim3(FFND/64, MTOK/128), 256>>>(x, w1, bf1, ffn, MTOK, FFND, HID);
        sgemm_bias_kernel<false><<<dim3(HID/64, MTOK/128), 256>>>(ffn, w2, bf2, tmp, MTOK, HID, FFND);
        add_ln_kernel<<<MTOK, 256>>>(x, tmp, s2, b2);
    }

    cls_kernel<<<MTOK, 288>>>(x, Wcls, bcls, lg, out_logits);
    crf_kernel<<<1, 256>>>(lg, labels, cst, cen, ctr, out_loss);
}

// round 3
// speedup vs baseline: 4.2967x; 4.2967x over previous
#include <cuda_runtime.h>
#include <cuda_fp16.h>
#include <mma.h>
#include <math.h>

using namespace nvcuda;

// ---------------------------------------------------------------------------
// Problem dims
// ---------------------------------------------------------------------------
#define BB   16
#define SS   256
#define NH   12
#define HD   64
#define HID  768
#define FFND 3072
#define NL   6
#define NT   9
#define MTOK (BB*SS)          // 4096 tokens
#define QKVW 2304             // 3*HID

// ---------------------------------------------------------------------------
// Scratch (device globals)
// ---------------------------------------------------------------------------
__device__ float  g_x    [MTOK*HID];      // fp32 residual stream
__device__ __half g_xh   [MTOK*HID];      // fp16 mirror of residual
__device__ __half g_qkvh [MTOK*QKVW];     // fp16 qkv projections
__device__ float  g_att  [BB*NH*SS*SS];   // fp32 attention scores
__device__ __half g_probs[BB*NH*SS*SS];   // fp16 attention probs
__device__ __half g_oh   [MTOK*HID];      // fp16 attention output
__device__ __half g_ffnh [MTOK*FFND];     // fp16 ffn intermediate
__device__ float  g_tmp  [MTOK*HID];      // fp32 gemm output (pre-residual)
__device__ float  g_lg   [MTOK*NT];       // logits
// fp16 weights (converted every launch)
__device__ __half g_WqkvH[NL*HID*QKVW];
__device__ __half g_WoH  [NL*HID*HID];
__device__ __half g_Wff1H[NL*HID*FFND];
__device__ __half g_Wff2H[NL*FFND*HID];

// ---------------------------------------------------------------------------
// fp32 -> fp16 conversion (grid-stride)
// ---------------------------------------------------------------------------
__global__ __launch_bounds__(256) void f2h_kernel(
    const float* __restrict__ src, __half* __restrict__ dst, long n)
{
    for (long i = blockIdx.x*256L + threadIdx.x; i < n; i += gridDim.x*256L)
        dst[i] = __float2half_rn(src[i]);
}

// ---------------------------------------------------------------------------
// Block-wide sum over 256 threads
// ---------------------------------------------------------------------------
__device__ __forceinline__ float blk_sum256(float v) {
    __shared__ float sm[8];
    #pragma unroll
    for (int o = 16; o; o >>= 1) v += __shfl_xor_sync(0xffffffffu, v, o);
    if ((threadIdx.x & 31) == 0) sm[threadIdx.x >> 5] = v;
    __syncthreads();
    float tot = 0.f;
    #pragma unroll
    for (int i = 0; i < 8; i++) tot += sm[i];
    __syncthreads();
    return tot;
}

// ---------------------------------------------------------------------------
// Embedding gather + LayerNorm.  grid = 4096 x 256.  Writes fp32 + fp16.
// ---------------------------------------------------------------------------
__global__ __launch_bounds__(256) void embed_ln_kernel(
    const int* __restrict__ ids, const float* __restrict__ wemb,
    const float* __restrict__ pemb, const float* __restrict__ lns,
    const float* __restrict__ lnb, float* __restrict__ x,
    __half* __restrict__ xh)
{
    int tok = blockIdx.x;
    int sp  = tok % SS;
    long id = ids[tok];
    float v[3]; float s = 0.f;
    #pragma unroll
    for (int j = 0; j < 3; j++) {
        int idx = threadIdx.x + j*256;
        v[j] = wemb[id*HID + idx] + pemb[(long)sp*HID + idx];
        s += v[j];
    }
    float mean = blk_sum256(s) * (1.f/HID);
    float sv = 0.f;
    #pragma unroll
    for (int j = 0; j < 3; j++) { float d = v[j]-mean; sv += d*d; }
    float var = blk_sum256(sv) * (1.f/HID);
    float inv = rsqrtf(var + 1e-12f);
    #pragma unroll
    for (int j = 0; j < 3; j++) {
        int idx = threadIdx.x + j*256;
        float o = (v[j]-mean)*inv*lns[idx] + lnb[idx];
        x [(long)tok*HID + idx] = o;
        xh[(long)tok*HID + idx] = __float2half_rn(o);
    }
}

// ---------------------------------------------------------------------------
// WMMA GEMM  C[M,N] = act(A[M,K]fp16 @ W[K,N]fp16 + bias[N])
// BM=128, BN=64, BK=32, 256 thr (8 warps, 4x2), warp tile 32x32 (2x2 frags).
// OUT_HALF selects fp16 vs fp32 output; GELU fuses tanh-gelu.
// ---------------------------------------------------------------------------
#define GLDA 40   // A smem ld (32+8)
#define GLDB 72   // B smem ld (64+8)
#define GLDC 72   // C smem ld

template<bool GELU, bool OUT_HALF>
__global__ __launch_bounds__(256) void gemm_wmma_kernel(
    const __half* __restrict__ A, const __half* __restrict__ W,
    const float* __restrict__ bias, void* __restrict__ Cout,
    int M, int N, int K)
{
    __shared__ __align__(16) char smbuf[128*GLDC*4];   // 36864 B
    __half* As = (__half*)smbuf;                       // [128][GLDA]
    __half* Bs = (__half*)(smbuf + 128*GLDA*2);        // [32][GLDB]
    float*  Cs = (float*)smbuf;                        // [128][GLDC]

    int tid = threadIdx.x, wid = tid >> 5;
    int warpM = wid & 3;      // 4 in M, 32 rows each
    int warpN = wid >> 2;     // 2 in N, 32 cols each
    int row0 = blockIdx.y * 128, col0 = blockIdx.x * 64;

    wmma::fragment<wmma::accumulator,16,16,16,float> acc[2][2];
    #pragma unroll
    for (int i = 0; i < 2; i++)
        #pragma unroll
        for (int j = 0; j < 2; j++) wmma::fill_fragment(acc[i][j], 0.f);

    for (int k0 = 0; k0 < K; k0 += 32) {
        #pragma unroll
        for (int u = tid; u < 512; u += 256) {            // A: 128x32 halves
            int r = u >> 2, cq = u & 3;
            *(uint4*)&As[r*GLDA + cq*8] =
                *(const uint4*)&A[(long)(row0+r)*K + k0 + cq*8];
        }
        {                                                  // B: 32x64 halves
            int r = tid >> 3, cq = tid & 7;
            *(uint4*)&Bs[r*GLDB + cq*8] =
                *(const uint4*)&W[(long)(k0+r)*N + col0 + cq*8];
        }
        __syncthreads();
        #pragma unroll
        for (int kk = 0; kk < 32; kk += 16) {
            wmma::fragment<wmma::matrix_a,16,16,16,__half,wmma::row_major> af[2];
            wmma::fragment<wmma::matrix_b,16,16,16,__half,wmma::row_major> bf[2];
            #pragma unroll
            for (int i = 0; i < 2; i++)
                wmma::load_matrix_sync(af[i], &As[(warpM*32 + i*16)*GLDA + kk], GLDA);
            #pragma unroll
            for (int j = 0; j < 2; j++)
                wmma::load_matrix_sync(bf[j], &Bs[kk*GLDB + warpN*32 + j*16], GLDB);
            #pragma unroll
            for (int i = 0; i < 2; i++)
                #pragma unroll
                for (int j = 0; j < 2; j++)
                    wmma::mma_sync(acc[i][j], af[i], bf[j], acc[i][j]);
        }
        __syncthreads();
    }
    #pragma unroll
    for (int i = 0; i < 2; i++)
        #pragma unroll
        for (int j = 0; j < 2; j++)
            wmma::store_matrix_sync(&Cs[(warpM*32+i*16)*GLDC + warpN*32 + j*16],
                                    acc[i][j], GLDC, wmma::mem_row_major);
    __syncthreads();
    for (int u = tid; u < 128*64; u += 256) {
        int r = u >> 6, c = u & 63;
        float v = Cs[r*GLDC + c] + bias[col0 + c];
        if (GELU) {
            float t = tanhf(0.7978845608028654f * (v + 0.044715f*v*v*v));
            v = 0.5f * v * (1.f + t);
        }
        long off = (long)(row0+r)*N + col0 + c;
        if (OUT_HALF) ((__half*)Cout)[off] = __float2half_rn(v);
        else          ((float*) Cout)[off] = v;
    }
}

// ---------------------------------------------------------------------------
// WMMA attention scores: att[bh,q,k] = (q.k)/8 + (1-mask)*-1e9  (fp32 out)
// grid (ktile=4, qtile=4, bh=192), 256 thr.  BM=BN=64, K=64.
// Warp layout: 8 warps, warpM=wid&3 (16 rows), warpN=wid>>2 (32 cols), 1x2.
// ---------------------------------------------------------------------------
__global__ __launch_bounds__(256) void attn_scores_wmma(
    const __half* __restrict__ qkvh, const int* __restrict__ amask,
    float* __restrict__ att)
{
    __shared__ __align__(16) char smbuf[64*72*4];     // 18432 B
    __half* Qs = (__half*)smbuf;                      // [64][72]
    __half* Ks = (__half*)(smbuf + 64*72*2);          // [64][72] (rows = key idx)
    float*  Cs = (float*)smbuf;                       // [64][72]

    int bh = blockIdx.z, b = bh / NH, h = bh % NH;
    int q0 = blockIdx.y * 64, k0 = blockIdx.x * 64;
    int tid = threadIdx.x, wid = tid >> 5;
    int warpM = wid & 3, warpN = wid >> 2;

    const __half* qb = qkvh + (long)(b*SS)*QKVW + h*HD;
    const __half* kb = qkvh + (long)(b*SS)*QKVW + HID + h*HD;

    #pragma unroll
    for (int u = tid; u < 512; u += 256) {            // Q tile 64x64
        int r = u >> 3, cq = u & 7;
        *(uint4*)&Qs[r*72 + cq*8] = *(const uint4*)&qb[(long)(q0+r)*QKVW + cq*8];
    }
    #pragma unroll
    for (int u = tid; u < 512; u += 256) {            // K tile 64x64
        int r = u >> 3, cq = u & 7;
        *(uint4*)&Ks[r*72 + cq*8] = *(const uint4*)&kb[(long)(k0+r)*QKVW + cq*8];
    }
    __syncthreads();

    wmma::fragment<wmma::accumulator,16,16,16,float> acc[2];
    wmma::fill_fragment(acc[0], 0.f);
    wmma::fill_fragment(acc[1], 0.f);
    #pragma unroll
    for (int kk = 0; kk < 64; kk += 16) {
        wmma::fragment<wmma::matrix_a,16,16,16,__half,wmma::row_major> af;
        wmma::fragment<wmma::matrix_b,16,16,16,__half,wmma::col_major> bf[2];
        wmma::load_matrix_sync(af, &Qs[(warpM*16)*72 + kk], 72);
        #pragma unroll
        for (int j = 0; j < 2; j++)
            wmma::load_matrix_sync(bf[j], &Ks[(warpN*32 + j*16)*72 + kk], 72);
        wmma::mma_sync(acc[0], af, bf[0], acc[0]);
        wmma::mma_sync(acc[1], af, bf[1], acc[1]);
    }
    __syncthreads();
    wmma::store_matrix_sync(&Cs[(warpM*16)*72 + warpN*32],      acc[0], 72, wmma::mem_row_major);
    wmma::store_matrix_sync(&Cs[(warpM*16)*72 + warpN*32 + 16], acc[1], 72, wmma::mem_row_major);
    __syncthreads();
    for (int u = tid; u < 64*64; u += 256) {
        int r = u >> 6, c = u & 63;
        float mb = (1.f - (float)amask[b*SS + k0 + c]) * -1e9f;
        att[((long)bh*SS + q0 + r)*SS + k0 + c] = Cs[r*72 + c]*0.125f + mb;
    }
}

// ---------------------------------------------------------------------------
// Row softmax over 256 cols, fp32 in -> fp16 probs out.
// ---------------------------------------------------------------------------
__global__ __launch_bounds__(256) void softmax_kernel(
    const float* __restrict__ att, __half* __restrict__ probs)
{
    const float* p = att + (long)blockIdx.x * SS;
    float v = p[threadIdx.x];
    __shared__ float sm[8];
    float m = v;
    #pragma unroll
    for (int o = 16; o; o >>= 1) m = fmaxf(m, __shfl_xor_sync(0xffffffffu, m, o));
    if ((threadIdx.x & 31) == 0) sm[threadIdx.x >> 5] = m;
    __syncthreads();
    float mx = -1e30f;
    #pragma unroll
    for (int i = 0; i < 8; i++) mx = fmaxf(mx, sm[i]);
    __syncthreads();
    float e = expf(v - mx);
    float s = e;
    #pragma unroll
    for (int o = 16; o; o >>= 1) s += __shfl_xor_sync(0xffffffffu, s, o);
    if ((threadIdx.x & 31) == 0) sm[threadIdx.x >> 5] = s;
    __syncthreads();
    float tot = 0.f;
    #pragma unroll
    for (int i = 0; i < 8; i++) tot += sm[i];
    probs[(long)blockIdx.x*SS + threadIdx.x] = __float2half_rn(e / tot);
}

// ---------------------------------------------------------------------------
// WMMA AV: o[b,q,h*64+d] = sum_k probs[bh,q,k] * v[b,k,h,d]   (fp16 out)
// grid (qtile=4, bh=192), 256 thr.  BM=64(q), BN=64(d), K=256.
// ---------------------------------------------------------------------------
__global__ __launch_bounds__(256) void attn_av_wmma(
    const __half* __restrict__ probs, const __half* __restrict__ qkvh,
    __half* __restrict__ oh)
{
    __shared__ __align__(16) char smbuf[64*72*4];     // 18432 B
    __half* Ps = (__half*)smbuf;                      // [64][40]
    __half* Vs = (__half*)(smbuf + 64*40*2);          // [32][72]
    float*  Cs = (float*)smbuf;                       // [64][72]

    int bh = blockIdx.y, b = bh / NH, h = bh % NH;
    int q0 = blockIdx.x * 64;
    int tid = threadIdx.x, wid = tid >> 5;
    int warpM = wid & 3, warpN = wid >> 2;

    const __half* pr = probs + ((long)bh*SS + q0)*SS;
    const __half* vb = qkvh + (long)(b*SS)*QKVW + 2*HID + h*HD;

    wmma::fragment<wmma::accumulator,16,16,16,float> acc[2];
    wmma::fill_fragment(acc[0], 0.f);
    wmma::fill_fragment(acc[1], 0.f);

    for (int k0 = 0; k0 < SS; k0 += 32) {
        {                                              // P tile 64x32
            int r = tid >> 2, cq = tid & 3;
            *(uint4*)&Ps[r*40 + cq*8] = *(const uint4*)&pr[(long)r*SS + k0 + cq*8];
        }
        {                                              // V tile 32x64
            int r = tid >> 3, cq = tid & 7;
            *(uint4*)&Vs[r*72 + cq*8] = *(const uint4*)&vb[(long)(k0+r)*QKVW + cq*8];
        }
        __syncthreads();
        #pragma unroll
        for (int kk = 0; kk < 32; kk += 16) {
            wmma::fragment<wmma::matrix_a,16,16,16,__half,wmma::row_major> af;
            wmma::fragment<wmma::matrix_b,16,16,16,__half,wmma::row_major> bf[2];
            wmma::load_matrix_sync(af, &Ps[(warpM*16)*40 + kk], 40);
            #pragma unroll
            for (int j = 0; j < 2; j++)
                wmma::load_matrix_sync(bf[j], &Vs[kk*72 + warpN*32 + j*16], 72);
            wmma::mma_sync(acc[0], af, bf[0], acc[0]);
            wmma::mma_sync(acc[1], af, bf[1], acc[1]);
        }
        __syncthreads();
    }
    wmma::store_matrix_sync(&Cs[(warpM*16)*72 + warpN*32],      acc[0], 72, wmma::mem_row_major);
    wmma::store_matrix_sync(&Cs[(warpM*16)*72 + warpN*32 + 16], acc[1], 72, wmma::mem_row_major);
    __syncthreads();
    for (int u = tid; u < 64*64; u += 256) {
        int r = u >> 6, c = u & 63;
        oh[(long)(b*SS + q0 + r)*HID + h*HD + c] = __float2half_rn(Cs[r*72 + c]);
    }
}

// ---------------------------------------------------------------------------
// x = LN(x + y); writes fp32 residual and fp16 mirror.
// ---------------------------------------------------------------------------
__global__ __launch_bounds__(256) void add_ln_kernel(
    float* __restrict__ x, const float* __restrict__ y,
    const float* __restrict__ lns, const float* __restrict__ lnb,
    __half* __restrict__ xh)
{
    long base = (long)blockIdx.x * HID;
    float v[3]; float s = 0.f;
    #pragma unroll
    for (int j = 0; j < 3; j++) {
        int idx = threadIdx.x + j*256;
        v[j] = x[base+idx] + y[base+idx];
        s += v[j];
    }
    float mean = blk_sum256(s) * (1.f/HID);
    float sv = 0.f;
    #pragma unroll
    for (int j = 0; j < 3; j++) { float d = v[j]-mean; sv += d*d; }
    float var = blk_sum256(sv) * (1.f/HID);
    float inv = rsqrtf(var + 1e-12f);
    #pragma unroll
    for (int j = 0; j < 3; j++) {
        int idx = threadIdx.x + j*256;
        float o = (v[j]-mean)*inv*lns[idx] + lnb[idx];
        x [base+idx] = o;
        xh[base+idx] = __float2half_rn(o);
    }
}

// ---------------------------------------------------------------------------
// Classifier head (fp32).
// ---------------------------------------------------------------------------
__global__ __launch_bounds__(288) void cls_kernel(
    const float* __restrict__ x, const float* __restrict__ Wc,
    const float* __restrict__ bc, float* __restrict__ logits,
    float* __restrict__ out_l)
{
    __shared__ float xs[HID];
    int tok = blockIdx.x;
    for (int i = threadIdx.x; i < HID; i += blockDim.x) xs[i] = x[(long)tok*HID + i];
    __syncthreads();
    int w = threadIdx.x >> 5, lane = threadIdx.x & 31;
    if (w < NT) {
        float acc = 0.f;
        for (int i = lane; i < HID; i += 32) acc += xs[i] * Wc[i*NT + w];
        #pragma unroll
        for (int o = 16; o; o >>= 1) acc += __shfl_down_sync(0xffffffffu, acc, o);
        if (lane == 0) {
            float val = acc + bc[w];
            logits[tok*NT + w] = val;
            if (out_l) out_l[tok*NT + w] = val;
        }
    }
}

// ---------------------------------------------------------------------------
// CRF NLL (single block, mirrors reference exactly).
// ---------------------------------------------------------------------------
__global__ __launch_bounds__(256) void crf_kernel(
    const float* __restrict__ logits, const int* __restrict__ labels,
    const float* __restrict__ cst, const float* __restrict__ cen,
    const float* __restrict__ ctr, float* __restrict__ out_loss)
{
    __shared__ float sc[BB][NT];
    __shared__ float tr[NT*NT];
    __shared__ float st[NT], en[NT];
    __shared__ float nb[BB], dn[BB];
    int t = threadIdx.x;
    if (t < NT*NT) tr[t] = ctr[t];
    if (t < NT) { st[t] = cst[t]; en[t] = cen[t]; }
    __syncthreads();

    int b = t / NT, j = t % NT;
    if (t < BB*NT) sc[b][j] = st[j] + logits[(long)(b*SS)*NT + j];

    if (t < BB) {
        int bb = t;
        int lab0 = labels[bb*SS];
        int tag0 = (lab0 == -100) ? 0 : lab0;
        float num = st[tag0] + logits[(long)(bb*SS)*NT + tag0];
        int prev = tag0;
        int cnt = 1;
        for (int s = 1; s < SS; s++) {
            int lab = labels[bb*SS + s];
            bool m = (lab != -100);
            int tg = m ? lab : 0;
            if (m) {
                num += tr[prev*NT + tg] + logits[(long)(bb*SS + s)*NT + tg];
                cnt++;
            }
            prev = tg;
        }
        int se = cnt - 1;
        int lab_e = labels[bb*SS + se];
        int tag_e = (lab_e == -100) ? 0 : lab_e;
        if (se == 0) tag_e = tag0;
        num += en[tag_e];
        nb[bb] = num;
    }
    __syncthreads();

    for (int s = 1; s < SS; s++) {
        float nv = 0.f;
        if (t < BB*NT) {
            int lab = labels[b*SS + s];
            bool m = (lab != -100);
            float e  = logits[(long)(b*SS + s)*NT + j];
            float mx = -1e30f;
            #pragma unroll
            for (int i = 0; i < NT; i++) mx = fmaxf(mx, sc[b][i] + tr[i*NT + j]);
            float sum = 0.f;
            #pragma unroll
            for (int i = 0; i < NT; i++) sum += expf(sc[b][i] + tr[i*NT + j] - mx);
            float ns = mx + logf(sum) + e;
            nv = m ? ns : sc[b][j];
        }
        __syncthreads();
        if (t < BB*NT) sc[b][j] = nv;
        __syncthreads();
    }

    if (t < BB) {
        float mx = -1e30f;
        #pragma unroll
        for (int i = 0; i < NT; i++) mx = fmaxf(mx, sc[t][i] + en[i]);
        float sum = 0.f;
        #pragma unroll
        for (int i = 0; i < NT; i++) sum += expf(sc[t][i] + en[i] - mx);
        dn[t] = mx + logf(sum);
    }
    __syncthreads();
    if (t == 0 && out_loss) {
        float acc = 0.f;
        for (int i = 0; i < BB; i++) acc += nb[i] - dn[i];
        *out_loss = -acc / BB;
    }
}

// ---------------------------------------------------------------------------
// Launch
// ---------------------------------------------------------------------------
extern "C" void kernel_launch(void* const* d_in, const int* in_sizes, int n_in,
                              void* d_out, int out_size)
{
    const int*   ids   = (const int*)  d_in[0];
    const int*   amask = (const int*)  d_in[1];
    const int*   labels= (const int*)  d_in[2];
    const float* wemb  = (const float*)d_in[3];
    const float* pemb  = (const float*)d_in[4];
    const float* elns  = (const float*)d_in[5];
    const float* elnb  = (const float*)d_in[6];
    const float* Wqkv  = (const float*)d_in[7];
    const float* bqkv  = (const float*)d_in[8];
    const float* Wo    = (const float*)d_in[9];
    const float* bo    = (const float*)d_in[10];
    const float* ln1s  = (const float*)d_in[11];
    const float* ln1b  = (const float*)d_in[12];
    const float* Wff1  = (const float*)d_in[13];
    const float* bff1  = (const float*)d_in[14];
    const float* Wff2  = (const float*)d_in[15];
    const float* bff2  = (const float*)d_in[16];
    const float* ln2s  = (const float*)d_in[17];
    const float* ln2b  = (const float*)d_in[18];
    const float* Wcls  = (const float*)d_in[19];
    const float* bcls  = (const float*)d_in[20];
    const float* cst   = (const float*)d_in[21];
    const float* cen   = (const float*)d_in[22];
    const float* ctr   = (const float*)d_in[23];
    float* out = (float*)d_out;

    float  *x, *att, *tmp, *lg;
    __half *xh, *qkvh, *probs, *oh, *ffnh, *WqkvH, *WoH, *Wff1H, *Wff2H;
    cudaGetSymbolAddress((void**)&x,     g_x);
    cudaGetSymbolAddress((void**)&xh,    g_xh);
    cudaGetSymbolAddress((void**)&qkvh,  g_qkvh);
    cudaGetSymbolAddress((void**)&att,   g_att);
    cudaGetSymbolAddress((void**)&probs, g_probs);
    cudaGetSymbolAddress((void**)&oh,    g_oh);
    cudaGetSymbolAddress((void**)&ffnh,  g_ffnh);
    cudaGetSymbolAddress((void**)&tmp,   g_tmp);
    cudaGetSymbolAddress((void**)&lg,    g_lg);
    cudaGetSymbolAddress((void**)&WqkvH, g_WqkvH);
    cudaGetSymbolAddress((void**)&WoH,   g_WoH);
    cudaGetSymbolAddress((void**)&Wff1H, g_Wff1H);
    cudaGetSymbolAddress((void**)&Wff2H, g_Wff2H);

    int logits_off = out_size - MTOK*NT;
    float* out_logits = (logits_off >= 0) ? out + logits_off : nullptr;
    float* out_loss   = (logits_off >= 1) ? out : nullptr;

    // Weight conversion (every launch; caching across calls is not allowed)
    f2h_kernel<<<2048, 256>>>(Wqkv, WqkvH, (long)NL*HID*QKVW);
    f2h_kernel<<<2048, 256>>>(Wo,   WoH,   (long)NL*HID*HID);
    f2h_kernel<<<2048, 256>>>(Wff1, Wff1H, (long)NL*HID*FFND);
    f2h_kernel<<<2048, 256>>>(Wff2, Wff2H, (long)NL*FFND*HID);

    embed_ln_kernel<<<MTOK, 256>>>(ids, wemb, pemb, elns, elnb, x, xh);

    for (int l = 0; l < NL; l++) {
        const __half* wqkv = WqkvH + (long)l*HID*QKVW;
        const float*  bq   = bqkv  + (long)l*QKVW;
        const __half* wo   = WoH   + (long)l*HID*HID;
        const float*  bo_  = bo    + (long)l*HID;
        const float*  s1   = ln1s  + (long)l*HID;
        const float*  b1   = ln1b  + (long)l*HID;
        const __half* w1   = Wff1H + (long)l*HID*FFND;
        const float*  bf1  = bff1  + (long)l*FFND;
        const __half* w2   = Wff2H + (long)l*FFND*HID;
        const float*  bf2  = bff2  + (long)l*HID;
        const float*  s2   = ln2s  + (long)l*HID;
        const float*  b2   = ln2b  + (long)l*HID;

        gemm_wmma_kernel<false,true ><<<dim3(QKVW/64, MTOK/128), 256>>>(xh, wqkv, bq, qkvh, MTOK, QKVW, HID);
        attn_scores_wmma<<<dim3(SS/64, SS/64, BB*NH), 256>>>(qkvh, amask, att);
        softmax_kernel<<<BB*NH*SS, 256>>>(att, probs);
        attn_av_wmma<<<dim3(SS/64, BB*NH), 256>>>(probs, qkvh, oh);
        gemm_wmma_kernel<false,false><<<dim3(HID/64, MTOK/128), 256>>>(oh, wo, bo_, tmp, MTOK, HID, HID);
        add_ln_kernel<<<MTOK, 256>>>(x, tmp, s1, b1, xh);
        gemm_wmma_kernel<true ,true ><<<dim3(FFND/64, MTOK/128), 256>>>(xh, w1, bf1, ffnh, MTOK, FFND, HID);
        gemm_wmma_kernel<false,false><<<dim3(HID/64, MTOK/128), 256>>>(ffnh, w2, bf2, tmp, MTOK, HID, FFND);
        add_ln_kernel<<<MTOK, 256>>>(x, tmp, s2, b2, xh);
    }

    cls_kernel<<<MTOK, 288>>>(x, Wcls, bcls, lg, out_logits);
    crf_kernel<<<1, 256>>>(lg, labels, cst, cen, ctr, out_loss);
}

// round 5
// speedup vs baseline: 4.9092x; 1.1425x over previous
#include <cuda_runtime.h>
#include <cuda_fp16.h>
#include <mma.h>
#include <math.h>

using namespace nvcuda;

// ---------------------------------------------------------------------------
// Problem dims
// ---------------------------------------------------------------------------
#define BB   16
#define SS   256
#define NH   12
#define HD   64
#define HID  768
#define FFND 3072
#define NL   6
#define NT   9
#define MTOK (BB*SS)
#define QKVW 2304

// ---------------------------------------------------------------------------
// Scratch (device globals)
// ---------------------------------------------------------------------------
__device__ float  g_x    [MTOK*HID];
__device__ __half g_xh   [MTOK*HID];
__device__ __half g_qkvh [MTOK*QKVW];
__device__ __half g_oh   [MTOK*HID];
__device__ __half g_ffnh [MTOK*FFND];
__device__ float  g_tmp  [MTOK*HID];
__device__ float  g_lg   [MTOK*NT];
__device__ __half g_WqkvH[NL*HID*QKVW];
__device__ __half g_WoH  [NL*HID*HID];
__device__ __half g_Wff1H[NL*HID*FFND];
__device__ __half g_Wff2H[NL*FFND*HID];

// ---------------------------------------------------------------------------
// cp.async helpers
// ---------------------------------------------------------------------------
__device__ __forceinline__ void cp_async16(void* smem_ptr, const void* gptr) {
    unsigned saddr = (unsigned)__cvta_generic_to_shared(smem_ptr);
    asm volatile("cp.async.cg.shared.global [%0], [%1], 16;\n" :: "r"(saddr), "l"(gptr));
}
#define CP_COMMIT() asm volatile("cp.async.commit_group;\n")
#define CP_WAIT1()  asm volatile("cp.async.wait_group 1;\n")
#define CP_WAIT0()  asm volatile("cp.async.wait_group 0;\n")

// ---------------------------------------------------------------------------
// fp32 -> fp16 conversion (vectorized)
// ---------------------------------------------------------------------------
__global__ __launch_bounds__(256) void f2h_kernel(
    const float4* __restrict__ src, __half2* __restrict__ dst, long n4)
{
    for (long i = blockIdx.x*256L + threadIdx.x; i < n4; i += gridDim.x*256L) {
        float4 f = src[i];
        dst[2*i]   = __floats2half2_rn(f.x, f.y);
        dst[2*i+1] = __floats2half2_rn(f.z, f.w);
    }
}

// ---------------------------------------------------------------------------
// Block-wide sum over 256 threads
// ---------------------------------------------------------------------------
__device__ __forceinline__ float blk_sum256(float v) {
    __shared__ float sm[8];
    #pragma unroll
    for (int o = 16; o; o >>= 1) v += __shfl_xor_sync(0xffffffffu, v, o);
    if ((threadIdx.x & 31) == 0) sm[threadIdx.x >> 5] = v;
    __syncthreads();
    float tot = 0.f;
    #pragma unroll
    for (int i = 0; i < 8; i++) tot += sm[i];
    __syncthreads();
    return tot;
}

// ---------------------------------------------------------------------------
// Embedding gather + LayerNorm
// ---------------------------------------------------------------------------
__global__ __launch_bounds__(256) void embed_ln_kernel(
    const int* __restrict__ ids, const float* __restrict__ wemb,
    const float* __restrict__ pemb, const float* __restrict__ lns,
    const float* __restrict__ lnb, float* __restrict__ x,
    __half* __restrict__ xh)
{
    int tok = blockIdx.x;
    int sp  = tok % SS;
    long id = ids[tok];
    float v[3]; float s = 0.f;
    #pragma unroll
    for (int j = 0; j < 3; j++) {
        int idx = threadIdx.x + j*256;
        v[j] = wemb[id*HID + idx] + pemb[(long)sp*HID + idx];
        s += v[j];
    }
    float mean = blk_sum256(s) * (1.f/HID);
    float sv = 0.f;
    #pragma unroll
    for (int j = 0; j < 3; j++) { float d = v[j]-mean; sv += d*d; }
    float var = blk_sum256(sv) * (1.f/HID);
    float inv = rsqrtf(var + 1e-12f);
    #pragma unroll
    for (int j = 0; j < 3; j++) {
        int idx = threadIdx.x + j*256;
        float o = (v[j]-mean)*inv*lns[idx] + lnb[idx];
        x [(long)tok*HID + idx] = o;
        xh[(long)tok*HID + idx] = __float2half_rn(o);
    }
}

// ---------------------------------------------------------------------------
// WMMA GEMM  C[M,N] = act(A@W + bias)
// BM=128, BN=128, BK=32, 2-stage cp.async, 256 thr (8 warps 2x4, warp 64x32)
// ---------------------------------------------------------------------------
#define ALD 40
#define BLD 136
#define ASZ (128*ALD*2)   // 10240 B
#define BSZ (32*BLD*2)    // 8704 B
#define CLD 132
#define GEMM_SMEM (128*CLD*4)   // 67584 B (>= 2*ASZ+2*BSZ = 37888)

template<bool GELU, bool OUT_HALF>
__global__ __launch_bounds__(256) void gemm2_kernel(
    const __half* __restrict__ A, const __half* __restrict__ W,
    const float* __restrict__ bias, void* __restrict__ Cout,
    int M, int N, int K)
{
    extern __shared__ char smraw[];
    __half* As0 = (__half*)smraw;
    __half* As1 = (__half*)(smraw + ASZ);
    __half* Bs0 = (__half*)(smraw + 2*ASZ);
    __half* Bs1 = (__half*)(smraw + 2*ASZ + BSZ);
    float*  Cs  = (float*)smraw;

    int tid = threadIdx.x, wid = tid >> 5;
    int warpM = wid >> 2;        // 2 warps in M, 64 rows each
    int warpN = wid & 3;         // 4 warps in N, 32 cols each
    int row0 = blockIdx.y * 128, col0 = blockIdx.x * 128;

    wmma::fragment<wmma::accumulator,16,16,16,float> acc[4][2];
    #pragma unroll
    for (int i = 0; i < 4; i++)
        #pragma unroll
        for (int j = 0; j < 2; j++) wmma::fill_fragment(acc[i][j], 0.f);

    int NTk = K >> 5;
    // prefetch stage 0
    {
        #pragma unroll
        for (int i = 0; i < 2; i++) {
            int u = tid + i*256, r = u >> 2, cq = u & 3;
            cp_async16(&As0[r*ALD + cq*8], &A[(long)(row0+r)*K + cq*8]);
        }
        #pragma unroll
        for (int i = 0; i < 2; i++) {
            int u = tid + i*256, r = u >> 4, cq = u & 15;
            cp_async16(&Bs0[r*BLD + cq*8], &W[(long)r*N + col0 + cq*8]);
        }
        CP_COMMIT();
    }

    for (int kt = 0; kt < NTk; kt++) {
        __half* As = (kt & 1) ? As1 : As0;
        __half* Bs = (kt & 1) ? Bs1 : Bs0;
        if (kt + 1 < NTk) {
            __half* An = (kt & 1) ? As0 : As1;
            __half* Bn = (kt & 1) ? Bs0 : Bs1;
            int kc = (kt+1) << 5;
            #pragma unroll
            for (int i = 0; i < 2; i++) {
                int u = tid + i*256, r = u >> 2, cq = u & 3;
                cp_async16(&An[r*ALD + cq*8], &A[(long)(row0+r)*K + kc + cq*8]);
            }
            #pragma unroll
            for (int i = 0; i < 2; i++) {
                int u = tid + i*256, r = u >> 4, cq = u & 15;
                cp_async16(&Bn[r*BLD + cq*8], &W[(long)(kc+r)*N + col0 + cq*8]);
            }
            CP_COMMIT();
            CP_WAIT1();
        } else {
            CP_WAIT0();
        }
        __syncthreads();
        #pragma unroll
        for (int kk = 0; kk < 32; kk += 16) {
            wmma::fragment<wmma::matrix_b,16,16,16,__half,wmma::row_major> bf[2];
            #pragma unroll
            for (int j = 0; j < 2; j++)
                wmma::load_matrix_sync(bf[j], &Bs[kk*BLD + warpN*32 + j*16], BLD);
            #pragma unroll
            for (int i = 0; i < 4; i++) {
                wmma::fragment<wmma::matrix_a,16,16,16,__half,wmma::row_major> af;
                wmma::load_matrix_sync(af, &As[(warpM*64 + i*16)*ALD + kk], ALD);
                wmma::mma_sync(acc[i][0], af, bf[0], acc[i][0]);
                wmma::mma_sync(acc[i][1], af, bf[1], acc[i][1]);
            }
        }
        __syncthreads();
    }

    #pragma unroll
    for (int i = 0; i < 4; i++)
        #pragma unroll
        for (int j = 0; j < 2; j++)
            wmma::store_matrix_sync(&Cs[(warpM*64+i*16)*CLD + warpN*32 + j*16],
                                    acc[i][j], CLD, wmma::mem_row_major);
    __syncthreads();
    for (int u = tid; u < 128*128; u += 256) {
        int r = u >> 7, c = u & 127;
        float v = Cs[r*CLD + c] + bias[col0 + c];
        if (GELU) {
            float t = tanhf(0.7978845608028654f * (v + 0.044715f*v*v*v));
            v = 0.5f * v * (1.f + t);
        }
        long off = (long)(row0+r)*N + col0 + c;
        if (OUT_HALF) ((__half*)Cout)[off] = __float2half_rn(v);
        else          ((float*) Cout)[off] = v;
    }
}

// ---------------------------------------------------------------------------
// Fused attention: per (bh, 64-query tile): S=QK^T/8+mask -> softmax -> P@V
// grid (4, 192), 256 thr.  smem: Q[64][72] | K/V[256][72] | S[64][260] fp32
// ---------------------------------------------------------------------------
#define SLD 260
#define PLD 40
#define ATT_SMEM (9216 + 36864 + 66560)   // 112640 B

__global__ __launch_bounds__(256) void attn_fused_kernel(
    const __half* __restrict__ qkvh, const int* __restrict__ amask,
    __half* __restrict__ oh)
{
    extern __shared__ char smraw[];
    __half* Qs = (__half*)smraw;               // [64][72]; later Ph [64][40]
    __half* Ks = (__half*)(smraw + 9216);      // [256][72]; later Vs
    float*  Ss = (float*)(smraw + 9216 + 36864); // [64][260]

    int bh = blockIdx.y, b = bh / NH, h = bh % NH;
    int q0 = blockIdx.x * 64;
    int tid = threadIdx.x, wid = tid >> 5, lane = tid & 31;
    int warpM = wid & 1;        // 2 in M (32 query rows)
    int warpN = wid >> 1;       // 4 in N

    const __half* qb = qkvh + (long)(b*SS)*QKVW + h*HD;
    const __half* kb = qb + HID;
    const __half* vb = qb + 2*HID;

    // load Q (64x64) and K (256x64)
    #pragma unroll
    for (int u = tid; u < 512; u += 256) {
        int r = u >> 3, cq = u & 7;
        *(uint4*)&Qs[r*72 + cq*8] = *(const uint4*)&qb[(long)(q0+r)*QKVW + cq*8];
    }
    for (int u = tid; u < 2048; u += 256) {
        int r = u >> 3, cq = u & 7;
        *(uint4*)&Ks[r*72 + cq*8] = *(const uint4*)&kb[(long)r*QKVW + cq*8];
    }
    __syncthreads();

    // QK^T: out 64x256; warp tile 32x64 -> acc[2][4]
    {
        wmma::fragment<wmma::accumulator,16,16,16,float> acc[2][4];
        #pragma unroll
        for (int i = 0; i < 2; i++)
            #pragma unroll
            for (int j = 0; j < 4; j++) wmma::fill_fragment(acc[i][j], 0.f);
        #pragma unroll
        for (int kk = 0; kk < 64; kk += 16) {
            wmma::fragment<wmma::matrix_b,16,16,16,__half,wmma::col_major> bf[4];
            #pragma unroll
            for (int j = 0; j < 4; j++)
                wmma::load_matrix_sync(bf[j], &Ks[(warpN*64 + j*16)*72 + kk], 72);
            #pragma unroll
            for (int i = 0; i < 2; i++) {
                wmma::fragment<wmma::matrix_a,16,16,16,__half,wmma::row_major> af;
                wmma::load_matrix_sync(af, &Qs[(warpM*32 + i*16)*72 + kk], 72);
                #pragma unroll
                for (int j = 0; j < 4; j++)
                    wmma::mma_sync(acc[i][j], af, bf[j], acc[i][j]);
            }
        }
        #pragma unroll
        for (int i = 0; i < 2; i++)
            #pragma unroll
            for (int j = 0; j < 4; j++)
                wmma::store_matrix_sync(&Ss[(warpM*32+i*16)*SLD + warpN*64 + j*16],
                                        acc[i][j], SLD, wmma::mem_row_major);
    }
    __syncthreads();

    // softmax: warp wid handles rows wid*8 .. wid*8+7
    #pragma unroll
    for (int rr = 0; rr < 8; rr++) {
        int r = wid*8 + rr;
        float v[8];
        float mx = -1e30f;
        #pragma unroll
        for (int k = 0; k < 8; k++) {
            int c = lane + k*32;
            float mb = (1.f - (float)amask[b*SS + c]) * -1e9f;
            v[k] = Ss[r*SLD + c]*0.125f + mb;
            mx = fmaxf(mx, v[k]);
        }
        #pragma unroll
        for (int o = 16; o; o >>= 1) mx = fmaxf(mx, __shfl_xor_sync(0xffffffffu, mx, o));
        float sum = 0.f;
        #pragma unroll
        for (int k = 0; k < 8; k++) { v[k] = expf(v[k]-mx); sum += v[k]; }
        #pragma unroll
        for (int o = 16; o; o >>= 1) sum += __shfl_xor_sync(0xffffffffu, sum, o);
        float inv = 1.f / sum;
        #pragma unroll
        for (int k = 0; k < 8; k++) Ss[r*SLD + lane + k*32] = v[k]*inv;
    }
    __syncthreads();

    // load V (256x64) over K buffer
    for (int u = tid; u < 2048; u += 256) {
        int r = u >> 3, cq = u & 7;
        *(uint4*)&Ks[r*72 + cq*8] = *(const uint4*)&vb[(long)r*QKVW + cq*8];
    }
    // (sync happens at top of AV loop)

    // AV: out 64x64; warp tile 32x16 -> acc2[2]; K-loop 256 in chunks of 32
    wmma::fragment<wmma::accumulator,16,16,16,float> acc2[2];
    wmma::fill_fragment(acc2[0], 0.f);
    wmma::fill_fragment(acc2[1], 0.f);
    __half* Ph = Qs;   // reuse Q region: [64][40]
    for (int k0 = 0; k0 < SS; k0 += 32) {
        __syncthreads();   // prev-iter fragment loads complete; V load complete (1st iter)
        #pragma unroll
        for (int e = 0; e < 8; e++) {
            int idx = tid*8 + e;
            int r = idx >> 5, c = idx & 31;
            Ph[r*PLD + c] = __float2half_rn(Ss[r*SLD + k0 + c]);
        }
        __syncthreads();
        #pragma unroll
        for (int kk = 0; kk < 32; kk += 16) {
            wmma::fragment<wmma::matrix_b,16,16,16,__half,wmma::row_major> bf;
            wmma::load_matrix_sync(bf, &Ks[(k0+kk)*72 + warpN*16], 72);
            #pragma unroll
            for (int i = 0; i < 2; i++) {
                wmma::fragment<wmma::matrix_a,16,16,16,__half,wmma::row_major> af;
                wmma::load_matrix_sync(af, &Ph[(warpM*32 + i*16)*PLD + kk], PLD);
                wmma::mma_sync(acc2[i], af, bf, acc2[i]);
            }
        }
    }
    __syncthreads();
    #pragma unroll
    for (int i = 0; i < 2; i++)
        wmma::store_matrix_sync(&Ss[(warpM*32+i*16)*68 + warpN*16], acc2[i], 68,
                                wmma::mem_row_major);
    __syncthreads();
    for (int u = tid; u < 4096; u += 256) {
        int r = u >> 6, c = u & 63;
        oh[(long)(b*SS + q0 + r)*HID + h*HD + c] = __float2half_rn(Ss[r*68 + c]);
    }
}

// ---------------------------------------------------------------------------
// x = LN(x + y); writes fp32 residual and fp16 mirror
// ---------------------------------------------------------------------------
__global__ __launch_bounds__(256) void add_ln_kernel(
    float* __restrict__ x, const float* __restrict__ y,
    const float* __restrict__ lns, const float* __restrict__ lnb,
    __half* __restrict__ xh)
{
    long base = (long)blockIdx.x * HID;
    float v[3]; float s = 0.f;
    #pragma unroll
    for (int j = 0; j < 3; j++) {
        int idx = threadIdx.x + j*256;
        v[j] = x[base+idx] + y[base+idx];
        s += v[j];
    }
    float mean = blk_sum256(s) * (1.f/HID);
    float sv = 0.f;
    #pragma unroll
    for (int j = 0; j < 3; j++) { float d = v[j]-mean; sv += d*d; }
    float var = blk_sum256(sv) * (1.f/HID);
    float inv = rsqrtf(var + 1e-12f);
    #pragma unroll
    for (int j = 0; j < 3; j++) {
        int idx = threadIdx.x + j*256;
        float o = (v[j]-mean)*inv*lns[idx] + lnb[idx];
        x [base+idx] = o;
        xh[base+idx] = __float2half_rn(o);
    }
}

// ---------------------------------------------------------------------------
// Classifier head
// ---------------------------------------------------------------------------
__global__ __launch_bounds__(288) void cls_kernel(
    const float* __restrict__ x, const float* __restrict__ Wc,
    const float* __restrict__ bc, float* __restrict__ logits,
    float* __restrict__ out_l)
{
    __shared__ float xs[HID];
    int tok = blockIdx.x;
    for (int i = threadIdx.x; i < HID; i += blockDim.x) xs[i] = x[(long)tok*HID + i];
    __syncthreads();
    int w = threadIdx.x >> 5, lane = threadIdx.x & 31;
    if (w < NT) {
        float acc = 0.f;
        for (int i = lane; i < HID; i += 32) acc += xs[i] * Wc[i*NT + w];
        #pragma unroll
        for (int o = 16; o; o >>= 1) acc += __shfl_down_sync(0xffffffffu, acc, o);
        if (lane == 0) {
            float val = acc + bc[w];
            logits[tok*NT + w] = val;
            if (out_l) out_l[tok*NT + w] = val;
        }
    }
}

// ---------------------------------------------------------------------------
// CRF NLL (single block, mirrors reference exactly)
// ---------------------------------------------------------------------------
__global__ __launch_bounds__(256) void crf_kernel(
    const float* __restrict__ logits, const int* __restrict__ labels,
    const float* __restrict__ cst, const float* __restrict__ cen,
    const float* __restrict__ ctr, float* __restrict__ out_loss)
{
    __shared__ float sc[BB][NT];
    __shared__ float tr[NT*NT];
    __shared__ float st[NT], en[NT];
    __shared__ float nb[BB], dn[BB];
    int t = threadIdx.x;
    if (t < NT*NT) tr[t] = ctr[t];
    if (t < NT) { st[t] = cst[t]; en[t] = cen[t]; }
    __syncthreads();

    int b = t / NT, j = t % NT;
    if (t < BB*NT) sc[b][j] = st[j] + logits[(long)(b*SS)*NT + j];

    if (t < BB) {
        int bb = t;
        int lab0 = labels[bb*SS];
        int tag0 = (lab0 == -100) ? 0 : lab0;
        float num = st[tag0] + logits[(long)(bb*SS)*NT + tag0];
        int prev = tag0;
        int cnt = 1;
        for (int s = 1; s < SS; s++) {
            int lab = labels[bb*SS + s];
            bool m = (lab != -100);
            int tg = m ? lab : 0;
            if (m) {
                num += tr[prev*NT + tg] + logits[(long)(bb*SS + s)*NT + tg];
                cnt++;
            }
            prev = tg;
        }
        int se = cnt - 1;
        int lab_e = labels[bb*SS + se];
        int tag_e = (lab_e == -100) ? 0 : lab_e;
        if (se == 0) tag_e = tag0;
        num += en[tag_e];
        nb[bb] = num;
    }
    __syncthreads();

    for (int s = 1; s < SS; s++) {
        float nv = 0.f;
        if (t < BB*NT) {
            int lab = labels[b*SS + s];
            bool m = (lab != -100);
            float e  = logits[(long)(b*SS + s)*NT + j];
            float mx = -1e30f;
            #pragma unroll
            for (int i = 0; i < NT; i++) mx = fmaxf(mx, sc[b][i] + tr[i*NT + j]);
            float sum = 0.f;
            #pragma unroll
            for (int i = 0; i < NT; i++) sum += expf(sc[b][i] + tr[i*NT + j] - mx);
            float ns = mx + logf(sum) + e;
            nv = m ? ns : sc[b][j];
        }
        __syncthreads();
        if (t < BB*NT) sc[b][j] = nv;
        __syncthreads();
    }

    if (t < BB) {
        float mx = -1e30f;
        #pragma unroll
        for (int i = 0; i < NT; i++) mx = fmaxf(mx, sc[t][i] + en[i]);
        float sum = 0.f;
        #pragma unroll
        for (int i = 0; i < NT; i++) sum += expf(sc[t][i] + en[i] - mx);
        dn[t] = mx + logf(sum);
    }
    __syncthreads();
    if (t == 0 && out_loss) {
        float acc = 0.f;
        for (int i = 0; i < BB; i++) acc += nb[i] - dn[i];
        *out_loss = -acc / BB;
    }
}

// ---------------------------------------------------------------------------
// Launch
// ---------------------------------------------------------------------------
extern "C" void kernel_launch(void* const* d_in, const int* in_sizes, int n_in,
                              void* d_out, int out_size)
{
    const int*   ids   = (const int*)  d_in[0];
    const int*   amask = (const int*)  d_in[1];
    const int*   labels= (const int*)  d_in[2];
    const float* wemb  = (const float*)d_in[3];
    const float* pemb  = (const float*)d_in[4];
    const float* elns  = (const float*)d_in[5];
    const float* elnb  = (const float*)d_in[6];
    const float* Wqkv  = (const float*)d_in[7];
    const float* bqkv  = (const float*)d_in[8];
    const float* Wo    = (const float*)d_in[9];
    const float* bo    = (const float*)d_in[10];
    const float* ln1s  = (const float*)d_in[11];
    const float* ln1b  = (const float*)d_in[12];
    const float* Wff1  = (const float*)d_in[13];
    const float* bff1  = (const float*)d_in[14];
    const float* Wff2  = (const float*)d_in[15];
    const float* bff2  = (const float*)d_in[16];
    const float* ln2s  = (const float*)d_in[17];
    const float* ln2b  = (const float*)d_in[18];
    const float* Wcls  = (const float*)d_in[19];
    const float* bcls  = (const float*)d_in[20];
    const float* cst   = (const float*)d_in[21];
    const float* cen   = (const float*)d_in[22];
    const float* ctr   = (const float*)d_in[23];
    float* out = (float*)d_out;

    float  *x, *tmp, *lg;
    __half *xh, *qkvh, *oh, *ffnh, *WqkvH, *WoH, *Wff1H, *Wff2H;
    cudaGetSymbolAddress((void**)&x,     g_x);
    cudaGetSymbolAddress((void**)&xh,    g_xh);
    cudaGetSymbolAddress((void**)&qkvh,  g_qkvh);
    cudaGetSymbolAddress((void**)&oh,    g_oh);
    cudaGetSymbolAddress((void**)&ffnh,  g_ffnh);
    cudaGetSymbolAddress((void**)&tmp,   g_tmp);
    cudaGetSymbolAddress((void**)&lg,    g_lg);
    cudaGetSymbolAddress((void**)&WqkvH, g_WqkvH);
    cudaGetSymbolAddress((void**)&WoH,   g_WoH);
    cudaGetSymbolAddress((void**)&Wff1H, g_Wff1H);
    cudaGetSymbolAddress((void**)&Wff2H, g_Wff2H);

    // opt-in to large dynamic smem (idempotent, capture-legal host calls)
    (void)cudaFuncSetAttribute(gemm2_kernel<false,true >, cudaFuncAttributeMaxDynamicSharedMemorySize, GEMM_SMEM);
    (void)cudaFuncSetAttribute(gemm2_kernel<false,false>, cudaFuncAttributeMaxDynamicSharedMemorySize, GEMM_SMEM);
    (void)cudaFuncSetAttribute(gemm2_kernel<true ,true >, cudaFuncAttributeMaxDynamicSharedMemorySize, GEMM_SMEM);
    (void)cudaFuncSetAttribute(attn_fused_kernel, cudaFuncAttributeMaxDynamicSharedMemorySize, ATT_SMEM);

    int logits_off = out_size - MTOK*NT;
    float* out_logits = (logits_off >= 0) ? out + logits_off : nullptr;
    float* out_loss   = (logits_off >= 1) ? out : nullptr;

    // weight conversion (must repeat each launch)
    f2h_kernel<<<2048, 256>>>((const float4*)Wqkv, (__half2*)WqkvH, (long)NL*HID*QKVW/4);
    f2h_kernel<<<1024, 256>>>((const float4*)Wo,   (__half2*)WoH,   (long)NL*HID*HID/4);
    f2h_kernel<<<2048, 256>>>((const float4*)Wff1, (__half2*)Wff1H, (long)NL*HID*FFND/4);
    f2h_kernel<<<2048, 256>>>((const float4*)Wff2, (__half2*)Wff2H, (long)NL*FFND*HID/4);

    embed_ln_kernel<<<MTOK, 256>>>(ids, wemb, pemb, elns, elnb, x, xh);

    for (int l = 0; l < NL; l++) {
        const __half* wqkv = WqkvH + (long)l*HID*QKVW;
        const float*  bq   = bqkv  + (long)l*QKVW;
        const __half* wo   = WoH   + (long)l*HID*HID;
        const float*  bo_  = bo    + (long)l*HID;
        const float*  s1   = ln1s  + (long)l*HID;
        const float*  b1   = ln1b  + (long)l*HID;
        const __half* w1   = Wff1H + (long)l*HID*FFND;
        const float*  bf1  = bff1  + (long)l*FFND;
        const __half* w2   = Wff2H + (long)l*FFND*HID;
        const float*  bf2  = bff2  + (long)l*HID;
        const float*  s2   = ln2s  + (long)l*HID;
        const float*  b2   = ln2b  + (long)l*HID;

        gemm2_kernel<false,true ><<<dim3(QKVW/128, MTOK/128), 256, GEMM_SMEM>>>(xh, wqkv, bq, qkvh, MTOK, QKVW, HID);
        attn_fused_kernel<<<dim3(SS/64, BB*NH), 256, ATT_SMEM>>>(qkvh, amask, oh);
        gemm2_kernel<false,false><<<dim3(HID/128, MTOK/128), 256, GEMM_SMEM>>>(oh, wo, bo_, tmp, MTOK, HID, HID);
        add_ln_kernel<<<MTOK, 256>>>(x, tmp, s1, b1, xh);
        gemm2_kernel<true ,true ><<<dim3(FFND/128, MTOK/128), 256, GEMM_SMEM>>>(xh, w1, bf1, ffnh, MTOK, FFND, HID);
        gemm2_kernel<false,false><<<dim3(HID/128, MTOK/128), 256, GEMM_SMEM>>>(ffnh, w2, bf2, tmp, MTOK, HID, FFND);
        add_ln_kernel<<<MTOK, 256>>>(x, tmp, s2, b2, xh);
    }

    cls_kernel<<<MTOK, 288>>>(x, Wcls, bcls, lg, out_logits);
    crf_kernel<<<1, 256>>>(lg, labels, cst, cen, ctr, out_loss);
}

// round 6
// speedup vs baseline: 5.3415x; 1.0881x over previous
#include <cuda_runtime.h>
#include <cuda_fp16.h>
#include <mma.h>
#include <math.h>

using namespace nvcuda;

// ---------------------------------------------------------------------------
// Problem dims
// ---------------------------------------------------------------------------
#define BB   16
#define SS   256
#define NH   12
#define HD   64
#define HID  768
#define FFND 3072
#define NL   6
#define NT   9
#define MTOK (BB*SS)
#define QKVW 2304

// ---------------------------------------------------------------------------
// Scratch (device globals)
// ---------------------------------------------------------------------------
__device__ float  g_x    [MTOK*HID];
__device__ __half g_xh   [MTOK*HID];
__device__ __half g_qkvh [MTOK*QKVW];
__device__ __half g_oh   [MTOK*HID];
__device__ __half g_ffnh [MTOK*FFND];
__device__ float  g_tmp  [MTOK*HID];
__device__ float  g_lg   [MTOK*NT];
__device__ __half g_WqkvH[NL*HID*QKVW];
__device__ __half g_WoH  [NL*HID*HID];
__device__ __half g_Wff1H[NL*HID*FFND];
__device__ __half g_Wff2H[NL*FFND*HID];

// ---------------------------------------------------------------------------
// cp.async helpers
// ---------------------------------------------------------------------------
__device__ __forceinline__ void cp_async16(void* smem_ptr, const void* gptr) {
    unsigned saddr = (unsigned)__cvta_generic_to_shared(smem_ptr);
    asm volatile("cp.async.cg.shared.global [%0], [%1], 16;\n" :: "r"(saddr), "l"(gptr));
}
#define CP_COMMIT() asm volatile("cp.async.commit_group;\n")
#define CP_WAIT2()  asm volatile("cp.async.wait_group 2;\n")

// ---------------------------------------------------------------------------
// fp32 -> fp16 conversion (vectorized)
// ---------------------------------------------------------------------------
__global__ __launch_bounds__(256) void f2h_kernel(
    const float4* __restrict__ src, __half2* __restrict__ dst, long n4)
{
    for (long i = blockIdx.x*256L + threadIdx.x; i < n4; i += gridDim.x*256L) {
        float4 f = src[i];
        dst[2*i]   = __floats2half2_rn(f.x, f.y);
        dst[2*i+1] = __floats2half2_rn(f.z, f.w);
    }
}

// ---------------------------------------------------------------------------
// Block-wide sums
// ---------------------------------------------------------------------------
__device__ __forceinline__ float blk_sum256(float v) {
    __shared__ float sm[8];
    #pragma unroll
    for (int o = 16; o; o >>= 1) v += __shfl_xor_sync(0xffffffffu, v, o);
    if ((threadIdx.x & 31) == 0) sm[threadIdx.x >> 5] = v;
    __syncthreads();
    float tot = 0.f;
    #pragma unroll
    for (int i = 0; i < 8; i++) tot += sm[i];
    __syncthreads();
    return tot;
}

__device__ __forceinline__ float blk_sum192(float v) {
    __shared__ float sm[6];
    #pragma unroll
    for (int o = 16; o; o >>= 1) v += __shfl_xor_sync(0xffffffffu, v, o);
    if ((threadIdx.x & 31) == 0) sm[threadIdx.x >> 5] = v;
    __syncthreads();
    float tot = 0.f;
    #pragma unroll
    for (int i = 0; i < 6; i++) tot += sm[i];
    __syncthreads();
    return tot;
}

// ---------------------------------------------------------------------------
// Embedding gather + LayerNorm
// ---------------------------------------------------------------------------
__global__ __launch_bounds__(256) void embed_ln_kernel(
    const int* __restrict__ ids, const float* __restrict__ wemb,
    const float* __restrict__ pemb, const float* __restrict__ lns,
    const float* __restrict__ lnb, float* __restrict__ x,
    __half* __restrict__ xh)
{
    int tok = blockIdx.x;
    int sp  = tok % SS;
    long id = ids[tok];
    float v[3]; float s = 0.f;
    #pragma unroll
    for (int j = 0; j < 3; j++) {
        int idx = threadIdx.x + j*256;
        v[j] = wemb[id*HID + idx] + pemb[(long)sp*HID + idx];
        s += v[j];
    }
    float mean = blk_sum256(s) * (1.f/HID);
    float sv = 0.f;
    #pragma unroll
    for (int j = 0; j < 3; j++) { float d = v[j]-mean; sv += d*d; }
    float var = blk_sum256(sv) * (1.f/HID);
    float inv = rsqrtf(var + 1e-12f);
    #pragma unroll
    for (int j = 0; j < 3; j++) {
        int idx = threadIdx.x + j*256;
        float o = (v[j]-mean)*inv*lns[idx] + lnb[idx];
        x [(long)tok*HID + idx] = o;
        xh[(long)tok*HID + idx] = __float2half_rn(o);
    }
}

// ---------------------------------------------------------------------------
// WMMA GEMM  C[M,N] = act(A@W + bias)
// BM=128, BN=128, BK=32.  4 warps (128 thr), warp tile 64x64 (4x4 frags).
// 4-stage cp.async ring, prefetch distance 2, ONE __syncthreads per k-tile.
// ---------------------------------------------------------------------------
#define ALD 40                       // A smem ld (32+8 halves)
#define BLD 136                      // B smem ld (128+8 halves)
#define STG_A (128*ALD*2)            // 10240 B
#define STG_B (32*BLD*2)             // 8704 B
#define STG_SZ (STG_A+STG_B)         // 18944 B
#define CLD 132
#define GEMM_SMEM (4*STG_SZ)         // 75776 B (Cs 128*132*4=67584 fits)

template<bool GELU, bool OUT_HALF>
__global__ __launch_bounds__(128) void gemm3_kernel(
    const __half* __restrict__ A, const __half* __restrict__ W,
    const float* __restrict__ bias, void* __restrict__ Cout,
    int M, int N, int K)
{
    extern __shared__ char smraw[];
    float* Cs = (float*)smraw;

    int tid = threadIdx.x, wid = tid >> 5;
    int warpM = wid & 1;      // 2 warps in M, 64 rows each
    int warpN = wid >> 1;     // 2 warps in N, 64 cols each
    int row0 = blockIdx.y * 128, col0 = blockIdx.x * 128;

    wmma::fragment<wmma::accumulator,16,16,16,float> acc[4][4];
    #pragma unroll
    for (int i = 0; i < 4; i++)
        #pragma unroll
        for (int j = 0; j < 4; j++) wmma::fill_fragment(acc[i][j], 0.f);

    int NTk = K >> 5;

    // prefetch: tile kt -> stage kt & 3
    auto prefetch = [&](int kt) {
        __half* As = (__half*)(smraw + (kt & 3)*STG_SZ);
        __half* Bs = (__half*)(smraw + (kt & 3)*STG_SZ + STG_A);
        int k0 = kt << 5;
        #pragma unroll
        for (int i = 0; i < 4; i++) {             // A: 128x32 = 512 cp16
            int u = tid + i*128, r = u >> 2, cq = u & 3;
            cp_async16(&As[r*ALD + cq*8], &A[(long)(row0+r)*K + k0 + cq*8]);
        }
        #pragma unroll
        for (int i = 0; i < 4; i++) {             // B: 32x128 = 512 cp16
            int u = tid + i*128, r = u >> 4, cq = u & 15;
            cp_async16(&Bs[r*BLD + cq*8], &W[(long)(k0+r)*N + col0 + cq*8]);
        }
    };

    prefetch(0); CP_COMMIT();
    prefetch(1); CP_COMMIT();

    for (int kt = 0; kt < NTk; kt++) {
        // prefetch distance 2: writes stage (kt+2)&3, last read by compute(kt-2),
        // which all threads finished before the barrier of iteration kt-1.
        if (kt + 2 < NTk) prefetch(kt + 2);
        CP_COMMIT();                  // empty group near tail keeps numbering uniform
        CP_WAIT2();                   // tile kt resident (<=2 newer groups pending)
        __syncthreads();              // cross-thread visibility of stage kt
        __half* As = (__half*)(smraw + (kt & 3)*STG_SZ);
        __half* Bs = (__half*)(smraw + (kt & 3)*STG_SZ + STG_A);
        #pragma unroll
        for (int kk = 0; kk < 32; kk += 16) {
            wmma::fragment<wmma::matrix_b,16,16,16,__half,wmma::row_major> bf[4];
            #pragma unroll
            for (int j = 0; j < 4; j++)
                wmma::load_matrix_sync(bf[j], &Bs[kk*BLD + warpN*64 + j*16], BLD);
            #pragma unroll
            for (int i = 0; i < 4; i++) {
                wmma::fragment<wmma::matrix_a,16,16,16,__half,wmma::row_major> af;
                wmma::load_matrix_sync(af, &As[(warpM*64 + i*16)*ALD + kk], ALD);
                #pragma unroll
                for (int j = 0; j < 4; j++)
                    wmma::mma_sync(acc[i][j], af, bf[j], acc[i][j]);
            }
        }
    }

    __syncthreads();   // protect stage memory before Cs overlay
    #pragma unroll
    for (int i = 0; i < 4; i++)
        #pragma unroll
        for (int j = 0; j < 4; j++)
            wmma::store_matrix_sync(&Cs[(warpM*64+i*16)*CLD + warpN*64 + j*16],
                                    acc[i][j], CLD, wmma::mem_row_major);
    __syncthreads();

    // vectorized epilogue: 4096 float4 groups
    for (int u = tid; u < 4096; u += 128) {
        int r = u >> 5, c4 = (u & 31) << 2;
        float4 v = *(const float4*)&Cs[r*CLD + c4];
        float4 bv = *(const float4*)&bias[col0 + c4];
        v.x += bv.x; v.y += bv.y; v.z += bv.z; v.w += bv.w;
        if (GELU) {
            float t;
            t = tanhf(0.7978845608028654f*(v.x + 0.044715f*v.x*v.x*v.x)); v.x = 0.5f*v.x*(1.f+t);
            t = tanhf(0.7978845608028654f*(v.y + 0.044715f*v.y*v.y*v.y)); v.y = 0.5f*v.y*(1.f+t);
            t = tanhf(0.7978845608028654f*(v.z + 0.044715f*v.z*v.z*v.z)); v.z = 0.5f*v.z*(1.f+t);
            t = tanhf(0.7978845608028654f*(v.w + 0.044715f*v.w*v.w*v.w)); v.w = 0.5f*v.w*(1.f+t);
        }
        long off = (long)(row0+r)*N + col0 + c4;
        if (OUT_HALF) {
            __half2* d = (__half2*)((__half*)Cout + off);
            d[0] = __floats2half2_rn(v.x, v.y);
            d[1] = __floats2half2_rn(v.z, v.w);
        } else {
            *(float4*)((float*)Cout + off) = v;
        }
    }
}

// ---------------------------------------------------------------------------
// Fused attention: per (bh, 64-query tile): S=QK^T/8+mask -> softmax -> P@V
// grid (4, 192), 256 thr.  smem: Q[64][72] | K/V[256][72] | S[64][260] fp32
// ---------------------------------------------------------------------------
#define SLD 260
#define PLD 40
#define ATT_SMEM (9216 + 36864 + 66560)   // 112640 B

__global__ __launch_bounds__(256) void attn_fused_kernel(
    const __half* __restrict__ qkvh, const int* __restrict__ amask,
    __half* __restrict__ oh)
{
    extern __shared__ char smraw[];
    __half* Qs = (__half*)smraw;                 // [64][72]; later Ph [64][40]
    __half* Ks = (__half*)(smraw + 9216);        // [256][72]; later Vs
    float*  Ss = (float*)(smraw + 9216 + 36864); // [64][260]

    int bh = blockIdx.y, b = bh / NH, h = bh % NH;
    int q0 = blockIdx.x * 64;
    int tid = threadIdx.x, wid = tid >> 5, lane = tid & 31;
    int warpM = wid & 1;
    int warpN = wid >> 1;

    const __half* qb = qkvh + (long)(b*SS)*QKVW + h*HD;
    const __half* kb = qb + HID;
    const __half* vb = qb + 2*HID;

    #pragma unroll
    for (int u = tid; u < 512; u += 256) {
        int r = u >> 3, cq = u & 7;
        *(uint4*)&Qs[r*72 + cq*8] = *(const uint4*)&qb[(long)(q0+r)*QKVW + cq*8];
    }
    for (int u = tid; u < 2048; u += 256) {
        int r = u >> 3, cq = u & 7;
        *(uint4*)&Ks[r*72 + cq*8] = *(const uint4*)&kb[(long)r*QKVW + cq*8];
    }
    __syncthreads();

    // QK^T: 64x256
    {
        wmma::fragment<wmma::accumulator,16,16,16,float> acc[2][4];
        #pragma unroll
        for (int i = 0; i < 2; i++)
            #pragma unroll
            for (int j = 0; j < 4; j++) wmma::fill_fragment(acc[i][j], 0.f);
        #pragma unroll
        for (int kk = 0; kk < 64; kk += 16) {
            wmma::fragment<wmma::matrix_b,16,16,16,__half,wmma::col_major> bf[4];
            #pragma unroll
            for (int j = 0; j < 4; j++)
                wmma::load_matrix_sync(bf[j], &Ks[(warpN*64 + j*16)*72 + kk], 72);
            #pragma unroll
            for (int i = 0; i < 2; i++) {
                wmma::fragment<wmma::matrix_a,16,16,16,__half,wmma::row_major> af;
                wmma::load_matrix_sync(af, &Qs[(warpM*32 + i*16)*72 + kk], 72);
                #pragma unroll
                for (int j = 0; j < 4; j++)
                    wmma::mma_sync(acc[i][j], af, bf[j], acc[i][j]);
            }
        }
        #pragma unroll
        for (int i = 0; i < 2; i++)
            #pragma unroll
            for (int j = 0; j < 4; j++)
                wmma::store_matrix_sync(&Ss[(warpM*32+i*16)*SLD + warpN*64 + j*16],
                                        acc[i][j], SLD, wmma::mem_row_major);
    }
    __syncthreads();

    // softmax
    #pragma unroll
    for (int rr = 0; rr < 8; rr++) {
        int r = wid*8 + rr;
        float v[8];
        float mx = -1e30f;
        #pragma unroll
        for (int k = 0; k < 8; k++) {
            int c = lane + k*32;
            float mb = (1.f - (float)amask[b*SS + c]) * -1e9f;
            v[k] = Ss[r*SLD + c]*0.125f + mb;
            mx = fmaxf(mx, v[k]);
        }
        #pragma unroll
        for (int o = 16; o; o >>= 1) mx = fmaxf(mx, __shfl_xor_sync(0xffffffffu, mx, o));
        float sum = 0.f;
        #pragma unroll
        for (int k = 0; k < 8; k++) { v[k] = expf(v[k]-mx); sum += v[k]; }
        #pragma unroll
        for (int o = 16; o; o >>= 1) sum += __shfl_xor_sync(0xffffffffu, sum, o);
        float inv = 1.f / sum;
        #pragma unroll
        for (int k = 0; k < 8; k++) Ss[r*SLD + lane + k*32] = v[k]*inv;
    }
    __syncthreads();

    // V over K buffer
    for (int u = tid; u < 2048; u += 256) {
        int r = u >> 3, cq = u & 7;
        *(uint4*)&Ks[r*72 + cq*8] = *(const uint4*)&vb[(long)r*QKVW + cq*8];
    }

    // P@V
    wmma::fragment<wmma::accumulator,16,16,16,float> acc2[2];
    wmma::fill_fragment(acc2[0], 0.f);
    wmma::fill_fragment(acc2[1], 0.f);
    __half* Ph = Qs;
    for (int k0 = 0; k0 < SS; k0 += 32) {
        __syncthreads();
        #pragma unroll
        for (int e = 0; e < 8; e++) {
            int idx = tid*8 + e;
            int r = idx >> 5, c = idx & 31;
            Ph[r*PLD + c] = __float2half_rn(Ss[r*SLD + k0 + c]);
        }
        __syncthreads();
        #pragma unroll
        for (int kk = 0; kk < 32; kk += 16) {
            wmma::fragment<wmma::matrix_b,16,16,16,__half,wmma::row_major> bf;
            wmma::load_matrix_sync(bf, &Ks[(k0+kk)*72 + warpN*16], 72);
            #pragma unroll
            for (int i = 0; i < 2; i++) {
                wmma::fragment<wmma::matrix_a,16,16,16,__half,wmma::row_major> af;
                wmma::load_matrix_sync(af, &Ph[(warpM*32 + i*16)*PLD + kk], PLD);
                wmma::mma_sync(acc2[i], af, bf, acc2[i]);
            }
        }
    }
    __syncthreads();
    #pragma unroll
    for (int i = 0; i < 2; i++)
        wmma::store_matrix_sync(&Ss[(warpM*32+i*16)*68 + warpN*16], acc2[i], 68,
                                wmma::mem_row_major);
    __syncthreads();
    for (int u = tid; u < 4096; u += 256) {
        int r = u >> 6, c = u & 63;
        oh[(long)(b*SS + q0 + r)*HID + h*HD + c] = __float2half_rn(Ss[r*68 + c]);
    }
}

// ---------------------------------------------------------------------------
// x = LN(x + y); float4 vectorized, 192 threads (one float4 per thread)
// ---------------------------------------------------------------------------
__global__ __launch_bounds__(192) void add_ln_kernel(
    float* __restrict__ x, const float* __restrict__ y,
    const float* __restrict__ lns, const float* __restrict__ lnb,
    __half* __restrict__ xh)
{
    long base = (long)blockIdx.x * HID;
    int t = threadIdx.x;
    float4 xv = *(const float4*)(x + base + t*4);
    float4 yv = *(const float4*)(y + base + t*4);
    float a = xv.x+yv.x, b = xv.y+yv.y, c = xv.z+yv.z, d = xv.w+yv.w;
    float mean = blk_sum192(a+b+c+d) * (1.f/HID);
    float da = a-mean, db = b-mean, dc = c-mean, dd = d-mean;
    float var = blk_sum192(da*da + db*db + dc*dc + dd*dd) * (1.f/HID);
    float inv = rsqrtf(var + 1e-12f);
    float4 ls = *(const float4*)(lns + t*4);
    float4 lb = *(const float4*)(lnb + t*4);
    float o0 = da*inv*ls.x + lb.x;
    float o1 = db*inv*ls.y + lb.y;
    float o2 = dc*inv*ls.z + lb.z;
    float o3 = dd*inv*ls.w + lb.w;
    *(float4*)(x + base + t*4) = make_float4(o0, o1, o2, o3);
    __half2* xh2 = (__half2*)(xh + base) + t*2;
    xh2[0] = __floats2half2_rn(o0, o1);
    xh2[1] = __floats2half2_rn(o2, o3);
}

// ---------------------------------------------------------------------------
// Classifier head
// ---------------------------------------------------------------------------
__global__ __launch_bounds__(288) void cls_kernel(
    const float* __restrict__ x, const float* __restrict__ Wc,
    const float* __restrict__ bc, float* __restrict__ logits,
    float* __restrict__ out_l)
{
    __shared__ float xs[HID];
    int tok = blockIdx.x;
    for (int i = threadIdx.x; i < HID; i += blockDim.x) xs[i] = x[(long)tok*HID + i];
    __syncthreads();
    int w = threadIdx.x >> 5, lane = threadIdx.x & 31;
    if (w < NT) {
        float acc = 0.f;
        for (int i = lane; i < HID; i += 32) acc += xs[i] * Wc[i*NT + w];
        #pragma unroll
        for (int o = 16; o; o >>= 1) acc += __shfl_down_sync(0xffffffffu, acc, o);
        if (lane == 0) {
            float val = acc + bc[w];
            logits[tok*NT + w] = val;
            if (out_l) out_l[tok*NT + w] = val;
        }
    }
}

// ---------------------------------------------------------------------------
// CRF NLL (single block, mirrors reference exactly)
// ---------------------------------------------------------------------------
__global__ __launch_bounds__(256) void crf_kernel(
    const float* __restrict__ logits, const int* __restrict__ labels,
    const float* __restrict__ cst, const float* __restrict__ cen,
    const float* __restrict__ ctr, float* __restrict__ out_loss)
{
    __shared__ float sc[BB][NT];
    __shared__ float tr[NT*NT];
    __shared__ float st[NT], en[NT];
    __shared__ float nb[BB], dn[BB];
    int t = threadIdx.x;
    if (t < NT*NT) tr[t] = ctr[t];
    if (t < NT) { st[t] = cst[t]; en[t] = cen[t]; }
    __syncthreads();

    int b = t / NT, j = t % NT;
    if (t < BB*NT) sc[b][j] = st[j] + logits[(long)(b*SS)*NT + j];

    if (t < BB) {
        int bb = t;
        int lab0 = labels[bb*SS];
        int tag0 = (lab0 == -100) ? 0 : lab0;
        float num = st[tag0] + logits[(long)(bb*SS)*NT + tag0];
        int prev = tag0;
        int cnt = 1;
        for (int s = 1; s < SS; s++) {
            int lab = labels[bb*SS + s];
            bool m = (lab != -100);
            int tg = m ? lab : 0;
            if (m) {
                num += tr[prev*NT + tg] + logits[(long)(bb*SS + s)*NT + tg];
                cnt++;
            }
            prev = tg;
        }
        int se = cnt - 1;
        int lab_e = labels[bb*SS + se];
        int tag_e = (lab_e == -100) ? 0 : lab_e;
        if (se == 0) tag_e = tag0;
        num += en[tag_e];
        nb[bb] = num;
    }
    __syncthreads();

    for (int s = 1; s < SS; s++) {
        float nv = 0.f;
        if (t < BB*NT) {
            int lab = labels[b*SS + s];
            bool m = (lab != -100);
            float e  = logits[(long)(b*SS + s)*NT + j];
            float mx = -1e30f;
            #pragma unroll
            for (int i = 0; i < NT; i++) mx = fmaxf(mx, sc[b][i] + tr[i*NT + j]);
            float sum = 0.f;
            #pragma unroll
            for (int i = 0; i < NT; i++) sum += expf(sc[b][i] + tr[i*NT + j] - mx);
            float ns = mx + logf(sum) + e;
            nv = m ? ns : sc[b][j];
        }
        __syncthreads();
        if (t < BB*NT) sc[b][j] = nv;
        __syncthreads();
    }

    if (t < BB) {
        float mx = -1e30f;
        #pragma unroll
        for (int i = 0; i < NT; i++) mx = fmaxf(mx, sc[t][i] + en[i]);
        float sum = 0.f;
        #pragma unroll
        for (int i = 0; i < NT; i++) sum += expf(sc[t][i] + en[i] - mx);
        dn[t] = mx + logf(sum);
    }
    __syncthreads();
    if (t == 0 && out_loss) {
        float acc = 0.f;
        for (int i = 0; i < BB; i++) acc += nb[i] - dn[i];
        *out_loss = -acc / BB;
    }
}

// ---------------------------------------------------------------------------
// Launch
// ---------------------------------------------------------------------------
extern "C" void kernel_launch(void* const* d_in, const int* in_sizes, int n_in,
                              void* d_out, int out_size)
{
    const int*   ids   = (const int*)  d_in[0];
    const int*   amask = (const int*)  d_in[1];
    const int*   labels= (const int*)  d_in[2];
    const float* wemb  = (const float*)d_in[3];
    const float* pemb  = (const float*)d_in[4];
    const float* elns  = (const float*)d_in[5];
    const float* elnb  = (const float*)d_in[6];
    const float* Wqkv  = (const float*)d_in[7];
    const float* bqkv  = (const float*)d_in[8];
    const float* Wo    = (const float*)d_in[9];
    const float* bo    = (const float*)d_in[10];
    const float* ln1s  = (const float*)d_in[11];
    const float* ln1b  = (const float*)d_in[12];
    const float* Wff1  = (const float*)d_in[13];
    const float* bff1  = (const float*)d_in[14];
    const float* Wff2  = (const float*)d_in[15];
    const float* bff2  = (const float*)d_in[16];
    const float* ln2s  = (const float*)d_in[17];
    const float* ln2b  = (const float*)d_in[18];
    const float* Wcls  = (const float*)d_in[19];
    const float* bcls  = (const float*)d_in[20];
    const float* cst   = (const float*)d_in[21];
    const float* cen   = (const float*)d_in[22];
    const float* ctr   = (const float*)d_in[23];
    float* out = (float*)d_out;

    float  *x, *tmp, *lg;
    __half *xh, *qkvh, *oh, *ffnh, *WqkvH, *WoH, *Wff1H, *Wff2H;
    cudaGetSymbolAddress((void**)&x,     g_x);
    cudaGetSymbolAddress((void**)&xh,    g_xh);
    cudaGetSymbolAddress((void**)&qkvh,  g_qkvh);
    cudaGetSymbolAddress((void**)&oh,    g_oh);
    cudaGetSymbolAddress((void**)&ffnh,  g_ffnh);
    cudaGetSymbolAddress((void**)&tmp,   g_tmp);
    cudaGetSymbolAddress((void**)&lg,    g_lg);
    cudaGetSymbolAddress((void**)&WqkvH, g_WqkvH);
    cudaGetSymbolAddress((void**)&WoH,   g_WoH);
    cudaGetSymbolAddress((void**)&Wff1H, g_Wff1H);
    cudaGetSymbolAddress((void**)&Wff2H, g_Wff2H);

    (void)cudaFuncSetAttribute(gemm3_kernel<false,true >, cudaFuncAttributeMaxDynamicSharedMemorySize, GEMM_SMEM);
    (void)cudaFuncSetAttribute(gemm3_kernel<false,false>, cudaFuncAttributeMaxDynamicSharedMemorySize, GEMM_SMEM);
    (void)cudaFuncSetAttribute(gemm3_kernel<true ,true >, cudaFuncAttributeMaxDynamicSharedMemorySize, GEMM_SMEM);
    (void)cudaFuncSetAttribute(attn_fused_kernel, cudaFuncAttributeMaxDynamicSharedMemorySize, ATT_SMEM);

    int logits_off = out_size - MTOK*NT;
    float* out_logits = (logits_off >= 0) ? out + logits_off : nullptr;
    float* out_loss   = (logits_off >= 1) ? out : nullptr;

    f2h_kernel<<<2048, 256>>>((const float4*)Wqkv, (__half2*)WqkvH, (long)NL*HID*QKVW/4);
    f2h_kernel<<<1024, 256>>>((const float4*)Wo,   (__half2*)WoH,   (long)NL*HID*HID/4);
    f2h_kernel<<<2048, 256>>>((const float4*)Wff1, (__half2*)Wff1H, (long)NL*HID*FFND/4);
    f2h_kernel<<<2048, 256>>>((const float4*)Wff2, (__half2*)Wff2H, (long)NL*FFND*HID/4);

    embed_ln_kernel<<<MTOK, 256>>>(ids, wemb, pemb, elns, elnb, x, xh);

    for (int l = 0; l < NL; l++) {
        const __half* wqkv = WqkvH + (long)l*HID*QKVW;
        const float*  bq   = bqkv  + (long)l*QKVW;
        const __half* wo   = WoH   + (long)l*HID*HID;
        const float*  bo_  = bo    + (long)l*HID;
        const float*  s1   = ln1s  + (long)l*HID;
        const float*  b1   = ln1b  + (long)l*HID;
        const __half* w1   = Wff1H + (long)l*HID*FFND;
        const float*  bf1  = bff1  + (long)l*FFND;
        const __half* w2   = Wff2H + (long)l*FFND*HID;
        const float*  bf2  = bff2  + (long)l*HID;
        const float*  s2   = ln2s  + (long)l*HID;
        const float*  b2   = ln2b  + (long)l*HID;

        gemm3_kernel<false,true ><<<dim3(QKVW/128, MTOK/128), 128, GEMM_SMEM>>>(xh, wqkv, bq, qkvh, MTOK, QKVW, HID);
        attn_fused_kernel<<<dim3(SS/64, BB*NH), 256, ATT_SMEM>>>(qkvh, amask, oh);
        gemm3_kernel<false,false><<<dim3(HID/128, MTOK/128), 128, GEMM_SMEM>>>(oh, wo, bo_, tmp, MTOK, HID, HID);
        add_ln_kernel<<<MTOK, 192>>>(x, tmp, s1, b1, xh);
        gemm3_kernel<true ,true ><<<dim3(FFND/128, MTOK/128), 128, GEMM_SMEM>>>(xh, w1, bf1, ffnh, MTOK, FFND, HID);
        gemm3_kernel<false,false><<<dim3(HID/128, MTOK/128), 128, GEMM_SMEM>>>(ffnh, w2, bf2, tmp, MTOK, HID, FFND);
        add_ln_kernel<<<MTOK, 192>>>(x, tmp, s2, b2, xh);
    }

    cls_kernel<<<MTOK, 288>>>(x, Wcls, bcls, lg, out_logits);
    crf_kernel<<<1, 256>>>(lg, labels, cst, cen, ctr, out_loss);
}